// round 1
// baseline (speedup 1.0000x reference)
#include <cuda_runtime.h>
#include <math.h>

#define Bk 16
#define Sk 512
#define Dk 512
#define Hh 4
#define DKk 128
#define FFk 1024
#define Lk 4

// -------------------- scratch (device globals; no allocation allowed) ------
__device__ float g_h  [Bk*Sk*Dk];
__device__ float g_h2 [Bk*Sk*Dk];
__device__ float g_q  [Bk*Sk*Dk];
__device__ float g_k  [Bk*Sk*Dk];
__device__ float g_v  [Bk*Sk*Dk];
__device__ float g_ctx[Bk*Sk*Dk];
__device__ float g_sc [(size_t)Bk*Hh*Sk*Sk];
__device__ float g_ff [Bk*Sk*FFk];
__device__ float g_o1 [Bk*Sk*Dk];
__device__ float g_o2 [Bk*Sk*(Dk/2)];

// -------------------- reductions --------------------
__device__ __forceinline__ float warpReduceSum(float v){
    #pragma unroll
    for (int o = 16; o > 0; o >>= 1) v += __shfl_xor_sync(0xffffffffu, v, o);
    return v;
}
__device__ __forceinline__ float warpReduceMax(float v){
    #pragma unroll
    for (int o = 16; o > 0; o >>= 1) v = fmaxf(v, __shfl_xor_sync(0xffffffffu, v, o));
    return v;
}

// -------------------- input projection: h = x@in_w + in_b + cond@cond_w + cond_b
__global__ void input_proj_kernel(const float* __restrict__ x,
                                  const float* __restrict__ cond,
                                  const float* __restrict__ in_w,
                                  const float* __restrict__ in_b,
                                  const float* __restrict__ cond_w,
                                  const float* __restrict__ cond_b,
                                  float* __restrict__ h)
{
    __shared__ float xs[18];
    __shared__ float cs[89];
    int tok = blockIdx.x;
    int t = threadIdx.x;          // 512 threads
    if (t < 18) xs[t] = x[(size_t)tok * 18 + t];
    if (t < 89) cs[t] = cond[(size_t)tok * 89 + t];
    __syncthreads();
    float acc = in_b[t] + cond_b[t];
    #pragma unroll 6
    for (int k = 0; k < 18; k++) acc += xs[k] * in_w[k * Dk + t];
    #pragma unroll 8
    for (int k = 0; k < 89; k++) acc += cs[k] * cond_w[k * Dk + t];
    h[(size_t)tok * Dk + t] = acc;
}

// -------------------- instance norm over channel dim (512) per token ------
__global__ void inorm_kernel(const float* __restrict__ x, float* __restrict__ y)
{
    __shared__ float s1[8], s2[8];
    const size_t base = (size_t)blockIdx.x * Dk;
    int t = threadIdx.x;          // 256 threads
    float a = x[base + t], b = x[base + t + 256];
    float sum = a + b;
    float sq  = a * a + b * b;
    sum = warpReduceSum(sum);
    sq  = warpReduceSum(sq);
    if ((t & 31) == 0) { s1[t >> 5] = sum; s2[t >> 5] = sq; }
    __syncthreads();
    if (t < 32) {
        float v1 = (t < 8) ? s1[t] : 0.f;
        float v2 = (t < 8) ? s2[t] : 0.f;
        v1 = warpReduceSum(v1);
        v2 = warpReduceSum(v2);
        if (t == 0) { s1[0] = v1; s2[0] = v2; }
    }
    __syncthreads();
    float mean = s1[0] * (1.f / Dk);
    float var  = s2[0] * (1.f / Dk) - mean * mean;
    float r = rsqrtf(var + 1e-5f);
    y[base + t]       = (a - mean) * r;
    y[base + t + 256] = (b - mean) * r;
}

// -------------------- generic SGEMM: C[M,N] (+)= A[M,K] @ B[K,N] (+bias)(relu)
// block tile 128x128, K-step 8, 256 threads, 8x8 per thread.
template<bool BIAS, bool RELU, bool ACCUM>
__global__ void __launch_bounds__(256, 2)
sgemm_kernel(const float* __restrict__ A, const float* __restrict__ B,
             const float* __restrict__ bias, float* __restrict__ C,
             int M, int N, int K)
{
    __shared__ float As[8][128];
    __shared__ float Bs[8][128];
    const int tid = threadIdx.x;
    const int bm = blockIdx.y * 128;
    const int bn = blockIdx.x * 128;
    const int arow = tid >> 1;
    const int acol = (tid & 1) * 4;
    const int brow = tid >> 5;
    const int bcol = (tid & 31) * 4;
    const int ty = (tid >> 4) * 8;
    const int tx = (tid & 15) * 8;
    float acc[8][8];
    #pragma unroll
    for (int i = 0; i < 8; i++)
        #pragma unroll
        for (int j = 0; j < 8; j++) acc[i][j] = 0.f;

    for (int kt = 0; kt < K; kt += 8) {
        float4 av = *(const float4*)(A + (size_t)(bm + arow) * K + kt + acol);
        As[acol + 0][arow] = av.x;
        As[acol + 1][arow] = av.y;
        As[acol + 2][arow] = av.z;
        As[acol + 3][arow] = av.w;
        float4 bv = *(const float4*)(B + (size_t)(kt + brow) * N + bn + bcol);
        *(float4*)&Bs[brow][bcol] = bv;
        __syncthreads();
        #pragma unroll
        for (int k = 0; k < 8; k++) {
            float ar[8], br[8];
            #pragma unroll
            for (int i = 0; i < 8; i++) ar[i] = As[k][ty + i];
            #pragma unroll
            for (int j = 0; j < 8; j++) br[j] = Bs[k][tx + j];
            #pragma unroll
            for (int i = 0; i < 8; i++)
                #pragma unroll
                for (int j = 0; j < 8; j++)
                    acc[i][j] = fmaf(ar[i], br[j], acc[i][j]);
        }
        __syncthreads();
    }

    #pragma unroll
    for (int i = 0; i < 8; i++) {
        const size_t row = (size_t)(bm + ty + i) * N + bn + tx;
        #pragma unroll
        for (int j = 0; j < 8; j += 4) {
            float4 r;
            r.x = acc[i][j + 0]; r.y = acc[i][j + 1];
            r.z = acc[i][j + 2]; r.w = acc[i][j + 3];
            if (BIAS) {
                r.x += bias[bn + tx + j + 0];
                r.y += bias[bn + tx + j + 1];
                r.z += bias[bn + tx + j + 2];
                r.w += bias[bn + tx + j + 3];
            }
            if (ACCUM) {
                float4 c = *(const float4*)(C + row + j);
                r.x += c.x; r.y += c.y; r.z += c.z; r.w += c.w;
            }
            if (RELU) {
                r.x = fmaxf(r.x, 0.f); r.y = fmaxf(r.y, 0.f);
                r.z = fmaxf(r.z, 0.f); r.w = fmaxf(r.w, 0.f);
            }
            *(float4*)(C + row + j) = r;
        }
    }
}

// -------------------- scores = (Q @ K^T)/sqrt(DK), masked -------------------
// grid: (S/64 k-tiles, S/64 q-tiles, B*H). 256 threads, 4x4 per thread.
__global__ void __launch_bounds__(256)
scores_kernel(const float* __restrict__ q, const float* __restrict__ k,
              const int* __restrict__ mask, float* __restrict__ scores)
{
    __shared__ float Qs[16][64];
    __shared__ float Ks[16][64];
    const int bh = blockIdx.z;
    const int b = bh / Hh;
    const int h = bh % Hh;
    const float* qp = q + (size_t)b * Sk * Dk + h * DKk;
    const float* kp = k + (size_t)b * Sk * Dk + h * DKk;
    const int q0 = blockIdx.y * 64;
    const int k0 = blockIdx.x * 64;
    const int tid = threadIdx.x;
    const int lr = tid >> 2;
    const int lc = (tid & 3) * 4;
    const int ty = (tid >> 4) * 4;
    const int tx = (tid & 15) * 4;
    float acc[4][4];
    #pragma unroll
    for (int i = 0; i < 4; i++)
        #pragma unroll
        for (int j = 0; j < 4; j++) acc[i][j] = 0.f;

    for (int kt = 0; kt < DKk; kt += 16) {
        float4 a = *(const float4*)(qp + (size_t)(q0 + lr) * Dk + kt + lc);
        Qs[lc + 0][lr] = a.x; Qs[lc + 1][lr] = a.y;
        Qs[lc + 2][lr] = a.z; Qs[lc + 3][lr] = a.w;
        float4 bb = *(const float4*)(kp + (size_t)(k0 + lr) * Dk + kt + lc);
        Ks[lc + 0][lr] = bb.x; Ks[lc + 1][lr] = bb.y;
        Ks[lc + 2][lr] = bb.z; Ks[lc + 3][lr] = bb.w;
        __syncthreads();
        #pragma unroll
        for (int kk = 0; kk < 16; kk++) {
            float a4[4], b4[4];
            #pragma unroll
            for (int i = 0; i < 4; i++) a4[i] = Qs[kk][ty + i];
            #pragma unroll
            for (int j = 0; j < 4; j++) b4[j] = Ks[kk][tx + j];
            #pragma unroll
            for (int i = 0; i < 4; i++)
                #pragma unroll
                for (int j = 0; j < 4; j++)
                    acc[i][j] = fmaf(a4[i], b4[j], acc[i][j]);
        }
        __syncthreads();
    }

    const float scale = 0.08838834764831845f; // 1/sqrt(128)
    #pragma unroll
    for (int i = 0; i < 4; i++) {
        const int qi = q0 + ty + i;
        const size_t srow = ((size_t)bh * Sk + qi) * Sk + k0 + tx;
        const size_t mrow = (size_t)b * Sk * Sk + (size_t)qi * Sk + k0 + tx;
        int4 mv = *(const int4*)(mask + mrow);
        float4 r;
        r.x = mv.x ? -1e9f : acc[i][0] * scale;
        r.y = mv.y ? -1e9f : acc[i][1] * scale;
        r.z = mv.z ? -1e9f : acc[i][2] * scale;
        r.w = mv.w ? -1e9f : acc[i][3] * scale;
        *(float4*)(scores + srow) = r;
    }
}

// -------------------- softmax over last dim (512), in place -----------------
__global__ void softmax_kernel(float* __restrict__ scores)
{
    __shared__ float red[8];
    float* row = scores + (size_t)blockIdx.x * Sk;
    int t = threadIdx.x;  // 256
    float v0 = row[t], v1 = row[t + 256];
    float m = fmaxf(v0, v1);
    m = warpReduceMax(m);
    if ((t & 31) == 0) red[t >> 5] = m;
    __syncthreads();
    if (t < 32) {
        float mm = (t < 8) ? red[t] : -3.4e38f;
        mm = warpReduceMax(mm);
        if (t == 0) red[0] = mm;
    }
    __syncthreads();
    m = red[0];
    __syncthreads();
    float e0 = __expf(v0 - m), e1 = __expf(v1 - m);
    float s = warpReduceSum(e0 + e1);
    if ((t & 31) == 0) red[t >> 5] = s;
    __syncthreads();
    if (t < 32) {
        float ss = (t < 8) ? red[t] : 0.f;
        ss = warpReduceSum(ss);
        if (t == 0) red[0] = ss;
    }
    __syncthreads();
    float inv = 1.f / red[0];
    row[t] = e0 * inv;
    row[t + 256] = e1 * inv;
}

// -------------------- ctx = P @ V (per b,h batch) ---------------------------
// grid: (DK/64, S/64, B*H). 256 threads, 4x4 per thread, K=512 step 16.
__global__ void __launch_bounds__(256)
attnv_kernel(const float* __restrict__ p, const float* __restrict__ v,
             float* __restrict__ ctx)
{
    __shared__ float As[16][64];
    __shared__ float Bs[16][64];
    const int bh = blockIdx.z;
    const int b = bh / Hh;
    const int h = bh % Hh;
    const float* pp = p + (size_t)bh * Sk * Sk;
    const float* vp = v + (size_t)b * Sk * Dk + h * DKk;
    const int q0 = blockIdx.y * 64;
    const int n0 = blockIdx.x * 64;
    const int tid = threadIdx.x;
    const int lr = tid >> 2;          // A: 64 rows x 16 cols
    const int lc = (tid & 3) * 4;
    const int br = tid >> 4;          // B: 16 rows x 64 cols
    const int bc = (tid & 15) * 4;
    const int ty = (tid >> 4) * 4;
    const int tx = (tid & 15) * 4;
    float acc[4][4];
    #pragma unroll
    for (int i = 0; i < 4; i++)
        #pragma unroll
        for (int j = 0; j < 4; j++) acc[i][j] = 0.f;

    for (int kt = 0; kt < Sk; kt += 16) {
        float4 a = *(const float4*)(pp + (size_t)(q0 + lr) * Sk + kt + lc);
        As[lc + 0][lr] = a.x; As[lc + 1][lr] = a.y;
        As[lc + 2][lr] = a.z; As[lc + 3][lr] = a.w;
        float4 bb = *(const float4*)(vp + (size_t)(kt + br) * Dk + n0 + bc);
        *(float4*)&Bs[br][bc] = bb;
        __syncthreads();
        #pragma unroll
        for (int kk = 0; kk < 16; kk++) {
            float a4[4], b4[4];
            #pragma unroll
            for (int i = 0; i < 4; i++) a4[i] = As[kk][ty + i];
            #pragma unroll
            for (int j = 0; j < 4; j++) b4[j] = Bs[kk][tx + j];
            #pragma unroll
            for (int i = 0; i < 4; i++)
                #pragma unroll
                for (int j = 0; j < 4; j++)
                    acc[i][j] = fmaf(a4[i], b4[j], acc[i][j]);
        }
        __syncthreads();
    }

    #pragma unroll
    for (int i = 0; i < 4; i++) {
        const size_t row = (size_t)b * Sk * Dk + (size_t)(q0 + ty + i) * Dk
                         + h * DKk + n0 + tx;
        float4 r;
        r.x = acc[i][0]; r.y = acc[i][1]; r.z = acc[i][2]; r.w = acc[i][3];
        *(float4*)(ctx + row) = r;
    }
}

// -------------------- final tiny head: [8192,256] @ [256,2] -----------------
__global__ void out3_kernel(const float* __restrict__ o2,
                            const float* __restrict__ w,
                            const float* __restrict__ b,
                            float* __restrict__ out)
{
    int idx = blockIdx.x * 256 + threadIdx.x;
    if (idx >= Bk * Sk * 2) return;
    int tok = idx >> 1, j = idx & 1;
    const float* o = o2 + (size_t)tok * 256;
    float acc = b[j];
    #pragma unroll 8
    for (int kk = 0; kk < 256; kk++) acc = fmaf(o[kk], w[kk * 2 + j], acc);
    out[idx] = acc;
}

// ============================ host launcher =================================
extern "C" void kernel_launch(void* const* d_in, const int* in_sizes, int n_in,
                              void* d_out, int out_size)
{
    const float* x      = (const float*)d_in[0];
    const float* cond   = (const float*)d_in[1];
    const int*   dmask  = (const int*)  d_in[2];
    const int*   smask  = (const int*)  d_in[3];
    const int*   gmask  = (const int*)  d_in[4];
    const float* attn_w = (const float*)d_in[5];
    const float* attn_b = (const float*)d_in[6];
    const float* ff_w1  = (const float*)d_in[7];
    const float* ff_b1  = (const float*)d_in[8];
    const float* ff_w2  = (const float*)d_in[9];
    const float* ff_b2  = (const float*)d_in[10];
    const float* in_w   = (const float*)d_in[11];
    const float* in_b   = (const float*)d_in[12];
    const float* cond_w = (const float*)d_in[13];
    const float* cond_b = (const float*)d_in[14];
    const float* out1_w = (const float*)d_in[15];
    const float* out1_b = (const float*)d_in[16];
    const float* out2_w = (const float*)d_in[17];
    const float* out2_b = (const float*)d_in[18];
    const float* out3_w = (const float*)d_in[19];
    const float* out3_b = (const float*)d_in[20];

    float *h, *h2, *q, *k, *v, *ctx, *sc, *ff, *o1, *o2;
    cudaGetSymbolAddress((void**)&h,   g_h);
    cudaGetSymbolAddress((void**)&h2,  g_h2);
    cudaGetSymbolAddress((void**)&q,   g_q);
    cudaGetSymbolAddress((void**)&k,   g_k);
    cudaGetSymbolAddress((void**)&v,   g_v);
    cudaGetSymbolAddress((void**)&ctx, g_ctx);
    cudaGetSymbolAddress((void**)&sc,  g_sc);
    cudaGetSymbolAddress((void**)&ff,  g_ff);
    cudaGetSymbolAddress((void**)&o1,  g_o1);
    cudaGetSymbolAddress((void**)&o2,  g_o2);

    const int M = Bk * Sk;           // 8192 tokens
    const int* masks[3] = { dmask, smask, gmask };

    input_proj_kernel<<<M, Dk>>>(x, cond, in_w, in_b, cond_w, cond_b, h);

    for (int l = 0; l < Lk; l++) {
        inorm_kernel<<<M, 256>>>(h, h2);
        for (int brn = 0; brn < 3; brn++) {
            const size_t wbase = (((size_t)l * 3 + brn) * 4) * Dk * Dk;
            const size_t bbase = (((size_t)l * 3 + brn) * 4) * Dk;
            const float* W  = attn_w + wbase;
            const float* Bb = attn_b + bbase;
            sgemm_kernel<true, false, false><<<dim3(4, 64), 256>>>(h2, W,              Bb,          q,  M, Dk, Dk);
            sgemm_kernel<true, false, false><<<dim3(4, 64), 256>>>(h2, W + 1*Dk*Dk,    Bb + 1*Dk,   k,  M, Dk, Dk);
            sgemm_kernel<true, false, false><<<dim3(4, 64), 256>>>(h2, W + 2*Dk*Dk,    Bb + 2*Dk,   v,  M, Dk, Dk);
            scores_kernel<<<dim3(Sk/64, Sk/64, Bk*Hh), 256>>>(q, k, masks[brn], sc);
            softmax_kernel<<<Bk*Hh*Sk, 256>>>(sc);
            attnv_kernel<<<dim3(DKk/64, Sk/64, Bk*Hh), 256>>>(sc, v, ctx);
            sgemm_kernel<true, false, true><<<dim3(4, 64), 256>>>(ctx, W + 3*Dk*Dk,    Bb + 3*Dk,   h,  M, Dk, Dk);
        }
        inorm_kernel<<<M, 256>>>(h, h2);
        sgemm_kernel<true, true,  false><<<dim3(8, 64), 256>>>(h2, ff_w1 + (size_t)l*Dk*FFk, ff_b1 + (size_t)l*FFk, ff, M, FFk, Dk);
        sgemm_kernel<true, false, true ><<<dim3(4, 64), 256>>>(ff, ff_w2 + (size_t)l*FFk*Dk, ff_b2 + (size_t)l*Dk,  h,  M, Dk, FFk);
    }

    sgemm_kernel<true, true, false><<<dim3(4, 64), 256>>>(h,  out1_w, out1_b, o1, M, Dk,    Dk);
    sgemm_kernel<true, true, false><<<dim3(2, 64), 256>>>(o1, out2_w, out2_b, o2, M, Dk/2,  Dk);
    out3_kernel<<<(M * 2 + 255) / 256, 256>>>(o2, out3_w, out3_b, (float*)d_out);
}

// round 3
// speedup vs baseline: 2.3384x; 2.3384x over previous
#include <cuda_runtime.h>
#include <cuda_bf16.h>
#include <cstdint>
#include <math.h>

#define Bk 16
#define Sk 512
#define Dk 512
#define Hh 4
#define DKk 128
#define FFk 1024
#define Lk 4

typedef __nv_bfloat16 bf16;
typedef __nv_bfloat162 bf162;

// ==================== scratch (device globals; no allocation) ===============
__device__ float g_h  [Bk*Sk*Dk];
__device__ float g_sc [(size_t)Bk*Hh*Sk*Sk];
__device__ float g_o1 [Bk*Sk*Dk];
__device__ float g_o2 [Bk*Sk*(Dk/2)];
// bf16 hi/lo activation splits
__device__ bf16 g_h2hi[Bk*Sk*Dk],  g_h2lo[Bk*Sk*Dk];
__device__ bf16 g_qhi [Bk*Sk*Dk],  g_qlo [Bk*Sk*Dk];
__device__ bf16 g_khi [Bk*Sk*Dk],  g_klo [Bk*Sk*Dk];
__device__ bf16 g_vhi [Bk*Sk*Dk],  g_vlo [Bk*Sk*Dk];
__device__ bf16 g_chi [Bk*Sk*Dk],  g_clo [Bk*Sk*Dk];
__device__ bf16 g_fhi [Bk*Sk*FFk], g_flo [Bk*Sk*FFk];
__device__ bf16 g_phi [(size_t)Bk*Hh*Sk*Sk], g_plo [(size_t)Bk*Hh*Sk*Sk];
// bf16 hi/lo weight splits (layouts identical to originals, [K][N] row-major)
__device__ bf16 g_awhi[(size_t)Lk*3*4*Dk*Dk], g_awlo[(size_t)Lk*3*4*Dk*Dk];
__device__ bf16 g_f1hi[(size_t)Lk*Dk*FFk],    g_f1lo[(size_t)Lk*Dk*FFk];
__device__ bf16 g_f2hi[(size_t)Lk*FFk*Dk],    g_f2lo[(size_t)Lk*FFk*Dk];

// ==================== low-level helpers =====================================
__device__ __forceinline__ uint32_t smem_u32(const void* p) {
    return (uint32_t)__cvta_generic_to_shared(p);
}
__device__ __forceinline__ void ldsm4(uint32_t* r, uint32_t addr) {
    asm volatile("ldmatrix.sync.aligned.m8n8.x4.shared.b16 {%0,%1,%2,%3}, [%4];"
        : "=r"(r[0]), "=r"(r[1]), "=r"(r[2]), "=r"(r[3]) : "r"(addr));
}
__device__ __forceinline__ void ldsm4t(uint32_t* r, uint32_t addr) {
    asm volatile("ldmatrix.sync.aligned.m8n8.x4.trans.shared.b16 {%0,%1,%2,%3}, [%4];"
        : "=r"(r[0]), "=r"(r[1]), "=r"(r[2]), "=r"(r[3]) : "r"(addr));
}
__device__ __forceinline__ void mma_bf16(float* c, const uint32_t* a,
                                         uint32_t b0, uint32_t b1) {
    asm volatile("mma.sync.aligned.m16n8k16.row.col.f32.bf16.bf16.f32 "
        "{%0,%1,%2,%3},{%4,%5,%6,%7},{%8,%9},{%0,%1,%2,%3};"
        : "+f"(c[0]), "+f"(c[1]), "+f"(c[2]), "+f"(c[3])
        : "r"(a[0]), "r"(a[1]), "r"(a[2]), "r"(a[3]), "r"(b0), "r"(b1));
}
__device__ __forceinline__ void cp16(uint32_t saddr, const bf16* g) {
    asm volatile("cp.async.cg.shared.global [%0], [%1], 16;"
        :: "r"(saddr), "l"(__cvta_generic_to_global(g)) : "memory");
}
#define CP_COMMIT()   asm volatile("cp.async.commit_group;" ::: "memory")
#define CP_WAIT(n)    asm volatile("cp.async.wait_group %0;" :: "n"(n) : "memory")

__device__ __forceinline__ void split_store2(bf16* hi, bf16* lo, size_t off,
                                             float x, float y) {
    bf16 hx = __float2bfloat16_rn(x);
    bf16 hy = __float2bfloat16_rn(y);
    bf162 hv; hv.x = hx; hv.y = hy;
    *(bf162*)(hi + off) = hv;
    bf162 lv;
    lv.x = __float2bfloat16_rn(x - __bfloat162float(hx));
    lv.y = __float2bfloat16_rn(y - __bfloat162float(hy));
    *(bf162*)(lo + off) = lv;
}

// ==================== smem tile loaders =====================================
// A-style tile: 128 rows x 32 bf16, row pitch 80B (conflict-free skew)
#define TA_BYTES 10240
__device__ __forceinline__ void cpA(uint32_t sbase, const bf16* g, int ld, int tid) {
    #pragma unroll
    for (int i = 0; i < 2; i++) {
        int idx = tid + i * 256;
        int r = idx >> 2, c = idx & 3;
        cp16(sbase + (uint32_t)(r * 80 + c * 16), g + (size_t)r * ld + c * 8);
    }
}
// B NN-style tile: 32 rows (k) x 128 bf16 (n), pitch 256B, XOR swizzle
#define TB_BYTES 8192
__device__ __forceinline__ void cpB_nn(uint32_t sbase, const bf16* g, int ld, int tid) {
    #pragma unroll
    for (int i = 0; i < 2; i++) {
        int idx = tid + i * 256;
        int k = idx >> 4, c = idx & 15;
        cp16(sbase + (uint32_t)(k * 256 + ((c ^ (k & 7)) << 4)),
             g + (size_t)k * ld + c * 8);
    }
}

// ==================== bf16x3 compute core ===================================
// NNB=true : B in NN layout ([k][n], trans ldmatrix).  false: NT ([n][k]).
template<bool NNB>
__device__ __forceinline__ void compute_stage(uint32_t aHi, uint32_t aLo,
        uint32_t bHi, uint32_t bLo, int wm, int wn, int lane, float acc[2][8][4])
{
    #pragma unroll
    for (int s = 0; s < 2; s++) {
        uint32_t ah[2][4], al[2][4], bh[4][4], bl[4][4];
        uint32_t aoff = (uint32_t)((wm + (lane & 15)) * 80 + (s * 2 + (lane >> 4)) * 16);
        ldsm4(ah[0], aHi + aoff);
        ldsm4(ah[1], aHi + aoff + 16 * 80);
        ldsm4(al[0], aLo + aoff);
        ldsm4(al[1], aLo + aoff + 16 * 80);
        if (NNB) {
            int k  = s * 16 + (lane & 7) + ((lane >> 3) & 1) * 8;
            int cb = (wn >> 3) + (lane >> 4);
            uint32_t ro = (uint32_t)(k * 256);
            #pragma unroll
            for (int t = 0; t < 4; t++) {
                uint32_t off = ro + (uint32_t)(((cb + t * 2) ^ (k & 7)) << 4);
                ldsm4t(bh[t], bHi + off);
            }
        } else {
            uint32_t boff = (uint32_t)((wn + (lane & 15)) * 80 + (s * 2 + (lane >> 4)) * 16);
            #pragma unroll
            for (int t = 0; t < 4; t++)
                ldsm4(bh[t], bHi + boff + t * 16 * 80);
        }
        // term1: Ahi*Bhi, term3: Alo*Bhi
        #pragma unroll
        for (int mt = 0; mt < 2; mt++)
            #pragma unroll
            for (int j = 0; j < 8; j++) {
                int t = j >> 1, o = j & 1;
                uint32_t b0, b1;
                if (NNB) { b0 = bh[t][o * 2]; b1 = bh[t][o * 2 + 1]; }
                else     { b0 = bh[t][o];     b1 = bh[t][o + 2];     }
                mma_bf16(acc[mt][j], ah[mt], b0, b1);
                mma_bf16(acc[mt][j], al[mt], b0, b1);
            }
        if (NNB) {
            int k  = s * 16 + (lane & 7) + ((lane >> 3) & 1) * 8;
            int cb = (wn >> 3) + (lane >> 4);
            uint32_t ro = (uint32_t)(k * 256);
            #pragma unroll
            for (int t = 0; t < 4; t++) {
                uint32_t off = ro + (uint32_t)(((cb + t * 2) ^ (k & 7)) << 4);
                ldsm4t(bl[t], bLo + off);
            }
        } else {
            uint32_t boff = (uint32_t)((wn + (lane & 15)) * 80 + (s * 2 + (lane >> 4)) * 16);
            #pragma unroll
            for (int t = 0; t < 4; t++)
                ldsm4(bl[t], bLo + boff + t * 16 * 80);
        }
        // term2: Ahi*Blo
        #pragma unroll
        for (int mt = 0; mt < 2; mt++)
            #pragma unroll
            for (int j = 0; j < 8; j++) {
                int t = j >> 1, o = j & 1;
                uint32_t b0, b1;
                if (NNB) { b0 = bl[t][o * 2]; b1 = bl[t][o * 2 + 1]; }
                else     { b0 = bl[t][o];     b1 = bl[t][o + 2];     }
                mma_bf16(acc[mt][j], ah[mt], b0, b1);
            }
    }
}

// ==================== wgemm: C[M,N] (+)= A[M,K] @ B[K,N] ====================
#define ST_NN   (2 * TA_BYTES + 2 * TB_BYTES)   // 36864
#define SM_NN   (2 * ST_NN)                     // 73728
template<bool RELU, bool ACCUM, bool OUTSPLIT>
__global__ void __launch_bounds__(256, 2)
wgemm_kernel(const bf16* __restrict__ Ahi, const bf16* __restrict__ Alo,
             const bf16* __restrict__ Bhi, const bf16* __restrict__ Blo,
             const float* __restrict__ bias,
             float* __restrict__ C, bf16* __restrict__ Chi, bf16* __restrict__ Clo,
             int M, int N, int K)
{
    extern __shared__ __align__(128) char smem[];
    const uint32_t sb = smem_u32(smem);
    const int tid = threadIdx.x, lane = tid & 31, w = tid >> 5;
    const int wm = (w & 3) * 32, wn = (w >> 2) * 64;
    const int bm = blockIdx.y * 128, bn = blockIdx.x * 128;
    const int NC = K >> 5;

    float acc[2][8][4];
    #pragma unroll
    for (int i = 0; i < 2; i++)
        #pragma unroll
        for (int j = 0; j < 8; j++)
            #pragma unroll
            for (int q = 0; q < 4; q++) acc[i][j][q] = 0.f;

    const bf16* Agh = Ahi + (size_t)bm * K;
    const bf16* Agl = Alo + (size_t)bm * K;
    const bf16* Bgh = Bhi + bn;
    const bf16* Bgl = Blo + bn;

    auto load = [&](int c, int stg) {
        uint32_t s0 = sb + stg * ST_NN;
        cpA   (s0,                 Agh + c * 32, K, tid);
        cpA   (s0 + TA_BYTES,      Agl + c * 32, K, tid);
        cpB_nn(s0 + 2 * TA_BYTES,            Bgh + (size_t)(c * 32) * N, N, tid);
        cpB_nn(s0 + 2 * TA_BYTES + TB_BYTES, Bgl + (size_t)(c * 32) * N, N, tid);
        CP_COMMIT();
    };

    load(0, 0);
    for (int c = 0; c < NC; c++) {
        if (c + 1 < NC) { load(c + 1, (c + 1) & 1); CP_WAIT(1); }
        else            { CP_WAIT(0); }
        __syncthreads();
        uint32_t s0 = sb + (c & 1) * ST_NN;
        compute_stage<true>(s0, s0 + TA_BYTES, s0 + 2 * TA_BYTES,
                            s0 + 2 * TA_BYTES + TB_BYTES, wm, wn, lane, acc);
        __syncthreads();
    }

    #pragma unroll
    for (int mt = 0; mt < 2; mt++) {
        int r0 = bm + wm + mt * 16 + (lane >> 2);
        #pragma unroll
        for (int j = 0; j < 8; j++) {
            int col = bn + wn + j * 8 + (lane & 3) * 2;
            float b0 = bias[col], b1 = bias[col + 1];
            float v00 = acc[mt][j][0] + b0, v01 = acc[mt][j][1] + b1;
            float v10 = acc[mt][j][2] + b0, v11 = acc[mt][j][3] + b1;
            size_t o0 = (size_t)r0 * N + col;
            size_t o1 = (size_t)(r0 + 8) * N + col;
            if (ACCUM) {
                float2 c0 = *(const float2*)(C + o0);
                float2 c1 = *(const float2*)(C + o1);
                v00 += c0.x; v01 += c0.y; v10 += c1.x; v11 += c1.y;
            }
            if (RELU) {
                v00 = fmaxf(v00, 0.f); v01 = fmaxf(v01, 0.f);
                v10 = fmaxf(v10, 0.f); v11 = fmaxf(v11, 0.f);
            }
            if (OUTSPLIT) {
                split_store2(Chi, Clo, o0, v00, v01);
                split_store2(Chi, Clo, o1, v10, v11);
            } else {
                float2 r; r.x = v00; r.y = v01; *(float2*)(C + o0) = r;
                float2 s; s.x = v10; s.y = v11; *(float2*)(C + o1) = s;
            }
        }
    }
}

// ==================== scores: sc = mask ? -1e9 : (Q@K^T)*scale ==============
#define ST_NT   (4 * TA_BYTES)      // 40960
#define SM_NT   (2 * ST_NT)         // 81920
__global__ void __launch_bounds__(256, 2)
scores_mma(const bf16* __restrict__ qhi, const bf16* __restrict__ qlo,
           const bf16* __restrict__ khi, const bf16* __restrict__ klo,
           const int* __restrict__ mask, float* __restrict__ sc)
{
    extern __shared__ __align__(128) char smem[];
    const uint32_t sb = smem_u32(smem);
    const int tid = threadIdx.x, lane = tid & 31, w = tid >> 5;
    const int wm = (w & 3) * 32, wn = (w >> 2) * 64;
    const int z = blockIdx.z, b = z >> 2, h = z & 3;
    const int bm = blockIdx.y * 128, bn = blockIdx.x * 128;
    const size_t qb = (size_t)b * Sk * Dk + h * DKk;

    float acc[2][8][4];
    #pragma unroll
    for (int i = 0; i < 2; i++)
        #pragma unroll
        for (int j = 0; j < 8; j++)
            #pragma unroll
            for (int q = 0; q < 4; q++) acc[i][j][q] = 0.f;

    const bf16* Qh = qhi + qb + (size_t)bm * Dk;
    const bf16* Ql = qlo + qb + (size_t)bm * Dk;
    const bf16* Kh = khi + qb + (size_t)bn * Dk;
    const bf16* Kl = klo + qb + (size_t)bn * Dk;

    auto load = [&](int c, int stg) {
        uint32_t s0 = sb + stg * ST_NT;
        cpA(s0,                Qh + c * 32, Dk, tid);
        cpA(s0 + TA_BYTES,     Ql + c * 32, Dk, tid);
        cpA(s0 + 2 * TA_BYTES, Kh + c * 32, Dk, tid);
        cpA(s0 + 3 * TA_BYTES, Kl + c * 32, Dk, tid);
        CP_COMMIT();
    };

    load(0, 0);
    const int NC = DKk >> 5;   // 4
    for (int c = 0; c < NC; c++) {
        if (c + 1 < NC) { load(c + 1, (c + 1) & 1); CP_WAIT(1); }
        else            { CP_WAIT(0); }
        __syncthreads();
        uint32_t s0 = sb + (c & 1) * ST_NT;
        compute_stage<false>(s0, s0 + TA_BYTES, s0 + 2 * TA_BYTES,
                             s0 + 3 * TA_BYTES, wm, wn, lane, acc);
        __syncthreads();
    }

    const float scale = 0.08838834764831845f;  // 1/sqrt(128)
    float* sp = sc + (size_t)z * Sk * Sk;
    const int* mp = mask + (size_t)b * Sk * Sk;
    #pragma unroll
    for (int mt = 0; mt < 2; mt++) {
        int r0 = bm + wm + mt * 16 + (lane >> 2);
        #pragma unroll
        for (int j = 0; j < 8; j++) {
            int col = bn + wn + j * 8 + (lane & 3) * 2;
            size_t o0 = (size_t)r0 * Sk + col;
            size_t o1 = (size_t)(r0 + 8) * Sk + col;
            int2 m0 = *(const int2*)(mp + o0);
            int2 m1 = *(const int2*)(mp + o1);
            float2 r, s;
            r.x = m0.x ? -1e9f : acc[mt][j][0] * scale;
            r.y = m0.y ? -1e9f : acc[mt][j][1] * scale;
            s.x = m1.x ? -1e9f : acc[mt][j][2] * scale;
            s.y = m1.y ? -1e9f : acc[mt][j][3] * scale;
            *(float2*)(sp + o0) = r;
            *(float2*)(sp + o1) = s;
        }
    }
}

// ==================== attnv: ctx = P @ V (split outputs) ====================
__global__ void __launch_bounds__(256, 2)
attnv_mma(const bf16* __restrict__ phi, const bf16* __restrict__ plo,
          const bf16* __restrict__ vhi, const bf16* __restrict__ vlo,
          bf16* __restrict__ chi, bf16* __restrict__ clo)
{
    extern __shared__ __align__(128) char smem[];
    const uint32_t sb = smem_u32(smem);
    const int tid = threadIdx.x, lane = tid & 31, w = tid >> 5;
    const int wm = (w & 3) * 32, wn = (w >> 2) * 64;
    const int z = blockIdx.z, b = z >> 2, h = z & 3;
    const int bm = blockIdx.y * 128;
    const size_t vb = (size_t)b * Sk * Dk + h * DKk;

    float acc[2][8][4];
    #pragma unroll
    for (int i = 0; i < 2; i++)
        #pragma unroll
        for (int j = 0; j < 8; j++)
            #pragma unroll
            for (int q = 0; q < 4; q++) acc[i][j][q] = 0.f;

    const bf16* Ph = phi + (size_t)z * Sk * Sk + (size_t)bm * Sk;
    const bf16* Pl = plo + (size_t)z * Sk * Sk + (size_t)bm * Sk;
    const bf16* Vh = vhi + vb;
    const bf16* Vl = vlo + vb;

    auto load = [&](int c, int stg) {
        uint32_t s0 = sb + stg * ST_NN;
        cpA   (s0,                 Ph + c * 32, Sk, tid);
        cpA   (s0 + TA_BYTES,      Pl + c * 32, Sk, tid);
        cpB_nn(s0 + 2 * TA_BYTES,            Vh + (size_t)(c * 32) * Dk, Dk, tid);
        cpB_nn(s0 + 2 * TA_BYTES + TB_BYTES, Vl + (size_t)(c * 32) * Dk, Dk, tid);
        CP_COMMIT();
    };

    load(0, 0);
    const int NC = Sk >> 5;  // 16
    for (int c = 0; c < NC; c++) {
        if (c + 1 < NC) { load(c + 1, (c + 1) & 1); CP_WAIT(1); }
        else            { CP_WAIT(0); }
        __syncthreads();
        uint32_t s0 = sb + (c & 1) * ST_NN;
        compute_stage<true>(s0, s0 + TA_BYTES, s0 + 2 * TA_BYTES,
                            s0 + 2 * TA_BYTES + TB_BYTES, wm, wn, lane, acc);
        __syncthreads();
    }

    bf16* ch = chi + vb;
    bf16* cl = clo + vb;
    #pragma unroll
    for (int mt = 0; mt < 2; mt++) {
        int r0 = bm + wm + mt * 16 + (lane >> 2);
        #pragma unroll
        for (int j = 0; j < 8; j++) {
            int col = wn + j * 8 + (lane & 3) * 2;   // 0..127 within head
            size_t o0 = (size_t)r0 * Dk + col;
            size_t o1 = (size_t)(r0 + 8) * Dk + col;
            split_store2(ch, cl, o0, acc[mt][j][0], acc[mt][j][1]);
            split_store2(ch, cl, o1, acc[mt][j][2], acc[mt][j][3]);
        }
    }
}

// ==================== weight split (elementwise, vectorized) ================
__global__ void wsplit_kernel(const float* __restrict__ w, bf16* __restrict__ hi,
                              bf16* __restrict__ lo)
{
    int i = (blockIdx.x * 256 + threadIdx.x) * 4;
    float4 v = *(const float4*)(w + i);
    split_store2(hi, lo, i,     v.x, v.y);
    split_store2(hi, lo, i + 2, v.z, v.w);
}

// ==================== reductions ============================================
__device__ __forceinline__ float warpReduceSum(float v) {
    #pragma unroll
    for (int o = 16; o > 0; o >>= 1) v += __shfl_xor_sync(0xffffffffu, v, o);
    return v;
}
__device__ __forceinline__ float warpReduceMax(float v) {
    #pragma unroll
    for (int o = 16; o > 0; o >>= 1) v = fmaxf(v, __shfl_xor_sync(0xffffffffu, v, o));
    return v;
}

// ==================== input projection ======================================
__global__ void input_proj_kernel(const float* __restrict__ x,
                                  const float* __restrict__ cond,
                                  const float* __restrict__ in_w,
                                  const float* __restrict__ in_b,
                                  const float* __restrict__ cond_w,
                                  const float* __restrict__ cond_b,
                                  float* __restrict__ h)
{
    __shared__ float xs[18];
    __shared__ float cs[89];
    int tok = blockIdx.x;
    int t = threadIdx.x;          // 512
    if (t < 18) xs[t] = x[(size_t)tok * 18 + t];
    if (t < 89) cs[t] = cond[(size_t)tok * 89 + t];
    __syncthreads();
    float acc = in_b[t] + cond_b[t];
    #pragma unroll 6
    for (int k = 0; k < 18; k++) acc += xs[k] * in_w[k * Dk + t];
    #pragma unroll 8
    for (int k = 0; k < 89; k++) acc += cs[k] * cond_w[k * Dk + t];
    h[(size_t)tok * Dk + t] = acc;
}

// ==================== instance norm (writes bf16 hi/lo split) ===============
__global__ void inorm_kernel(const float* __restrict__ x,
                             bf16* __restrict__ yhi, bf16* __restrict__ ylo)
{
    __shared__ float s1[8], s2[8];
    const size_t base = (size_t)blockIdx.x * Dk;
    int t = threadIdx.x;          // 256
    float a = x[base + t], b = x[base + t + 256];
    float sum = warpReduceSum(a + b);
    float sq  = warpReduceSum(a * a + b * b);
    if ((t & 31) == 0) { s1[t >> 5] = sum; s2[t >> 5] = sq; }
    __syncthreads();
    if (t < 32) {
        float v1 = (t < 8) ? s1[t] : 0.f;
        float v2 = (t < 8) ? s2[t] : 0.f;
        v1 = warpReduceSum(v1);
        v2 = warpReduceSum(v2);
        if (t == 0) { s1[0] = v1; s2[0] = v2; }
    }
    __syncthreads();
    float mean = s1[0] * (1.f / Dk);
    float var  = s2[0] * (1.f / Dk) - mean * mean;
    float r = rsqrtf(var + 1e-5f);
    float y0 = (a - mean) * r, y1 = (b - mean) * r;
    bf16 h0 = __float2bfloat16_rn(y0);
    bf16 h1 = __float2bfloat16_rn(y1);
    yhi[base + t]       = h0;
    yhi[base + t + 256] = h1;
    ylo[base + t]       = __float2bfloat16_rn(y0 - __bfloat162float(h0));
    ylo[base + t + 256] = __float2bfloat16_rn(y1 - __bfloat162float(h1));
}

// ==================== softmax (fp32 in, bf16 hi/lo out) =====================
__global__ void softmax_kernel(const float* __restrict__ scores,
                               bf16* __restrict__ phi, bf16* __restrict__ plo)
{
    __shared__ float red[8];
    const float* row = scores + (size_t)blockIdx.x * Sk;
    const size_t base = (size_t)blockIdx.x * Sk;
    int t = threadIdx.x;  // 256
    float v0 = row[t], v1 = row[t + 256];
    float m = warpReduceMax(fmaxf(v0, v1));
    if ((t & 31) == 0) red[t >> 5] = m;
    __syncthreads();
    if (t < 32) {
        float mm = (t < 8) ? red[t] : -3.4e38f;
        mm = warpReduceMax(mm);
        if (t == 0) red[0] = mm;
    }
    __syncthreads();
    m = red[0];
    __syncthreads();
    float e0 = __expf(v0 - m), e1 = __expf(v1 - m);
    float s = warpReduceSum(e0 + e1);
    if ((t & 31) == 0) red[t >> 5] = s;
    __syncthreads();
    if (t < 32) {
        float ss = (t < 8) ? red[t] : 0.f;
        ss = warpReduceSum(ss);
        if (t == 0) red[0] = ss;
    }
    __syncthreads();
    float inv = 1.f / red[0];
    float p0 = e0 * inv, p1 = e1 * inv;
    bf16 h0 = __float2bfloat16_rn(p0);
    bf16 h1 = __float2bfloat16_rn(p1);
    phi[base + t]       = h0;
    phi[base + t + 256] = h1;
    plo[base + t]       = __float2bfloat16_rn(p0 - __bfloat162float(h0));
    plo[base + t + 256] = __float2bfloat16_rn(p1 - __bfloat162float(h1));
}

// ==================== fp32 SGEMM (small output head) ========================
template<bool BIAS, bool RELU, bool ACCUM>
__global__ void __launch_bounds__(256, 2)
sgemm_kernel(const float* __restrict__ A, const float* __restrict__ B,
             const float* __restrict__ bias, float* __restrict__ C,
             int M, int N, int K)
{
    __shared__ float As[8][128];
    __shared__ float Bs[8][128];
    const int tid = threadIdx.x;
    const int bm = blockIdx.y * 128;
    const int bn = blockIdx.x * 128;
    const int arow = tid >> 1;
    const int acol = (tid & 1) * 4;
    const int brow = tid >> 5;
    const int bcol = (tid & 31) * 4;
    const int ty = (tid >> 4) * 8;
    const int tx = (tid & 15) * 8;
    float acc[8][8];
    #pragma unroll
    for (int i = 0; i < 8; i++)
        #pragma unroll
        for (int j = 0; j < 8; j++) acc[i][j] = 0.f;

    for (int kt = 0; kt < K; kt += 8) {
        float4 av = *(const float4*)(A + (size_t)(bm + arow) * K + kt + acol);
        As[acol + 0][arow] = av.x;
        As[acol + 1][arow] = av.y;
        As[acol + 2][arow] = av.z;
        As[acol + 3][arow] = av.w;
        float4 bv = *(const float4*)(B + (size_t)(kt + brow) * N + bn + bcol);
        *(float4*)&Bs[brow][bcol] = bv;
        __syncthreads();
        #pragma unroll
        for (int k = 0; k < 8; k++) {
            float ar[8], br[8];
            #pragma unroll
            for (int i = 0; i < 8; i++) ar[i] = As[k][ty + i];
            #pragma unroll
            for (int j = 0; j < 8; j++) br[j] = Bs[k][tx + j];
            #pragma unroll
            for (int i = 0; i < 8; i++)
                #pragma unroll
                for (int j = 0; j < 8; j++)
                    acc[i][j] = fmaf(ar[i], br[j], acc[i][j]);
        }
        __syncthreads();
    }

    #pragma unroll
    for (int i = 0; i < 8; i++) {
        const size_t row = (size_t)(bm + ty + i) * N + bn + tx;
        #pragma unroll
        for (int j = 0; j < 8; j += 4) {
            float4 r;
            r.x = acc[i][j + 0]; r.y = acc[i][j + 1];
            r.z = acc[i][j + 2]; r.w = acc[i][j + 3];
            if (BIAS) {
                r.x += bias[bn + tx + j + 0];
                r.y += bias[bn + tx + j + 1];
                r.z += bias[bn + tx + j + 2];
                r.w += bias[bn + tx + j + 3];
            }
            if (ACCUM) {
                float4 c = *(const float4*)(C + row + j);
                r.x += c.x; r.y += c.y; r.z += c.z; r.w += c.w;
            }
            if (RELU) {
                r.x = fmaxf(r.x, 0.f); r.y = fmaxf(r.y, 0.f);
                r.z = fmaxf(r.z, 0.f); r.w = fmaxf(r.w, 0.f);
            }
            *(float4*)(C + row + j) = r;
        }
    }
}

// ==================== final tiny head =======================================
__global__ void out3_kernel(const float* __restrict__ o2,
                            const float* __restrict__ w,
                            const float* __restrict__ b,
                            float* __restrict__ out)
{
    int idx = blockIdx.x * 256 + threadIdx.x;
    if (idx >= Bk * Sk * 2) return;
    int tok = idx >> 1, j = idx & 1;
    const float* o = o2 + (size_t)tok * 256;
    float acc = b[j];
    #pragma unroll 8
    for (int kk = 0; kk < 256; kk++) acc = fmaf(o[kk], w[kk * 2 + j], acc);
    out[idx] = acc;
}

// ============================ host launcher =================================
extern "C" void kernel_launch(void* const* d_in, const int* in_sizes, int n_in,
                              void* d_out, int out_size)
{
    const float* x      = (const float*)d_in[0];
    const float* cond   = (const float*)d_in[1];
    const int*   dmask  = (const int*)  d_in[2];
    const int*   smask  = (const int*)  d_in[3];
    const int*   gmask  = (const int*)  d_in[4];
    const float* attn_w = (const float*)d_in[5];
    const float* attn_b = (const float*)d_in[6];
    const float* ff_w1  = (const float*)d_in[7];
    const float* ff_b1  = (const float*)d_in[8];
    const float* ff_w2  = (const float*)d_in[9];
    const float* ff_b2  = (const float*)d_in[10];
    const float* in_w   = (const float*)d_in[11];
    const float* in_b   = (const float*)d_in[12];
    const float* cond_w = (const float*)d_in[13];
    const float* cond_b = (const float*)d_in[14];
    const float* out1_w = (const float*)d_in[15];
    const float* out1_b = (const float*)d_in[16];
    const float* out2_w = (const float*)d_in[17];
    const float* out2_b = (const float*)d_in[18];
    const float* out3_w = (const float*)d_in[19];
    const float* out3_b = (const float*)d_in[20];

    float *h, *sc, *o1, *o2;
    bf16 *h2hi, *h2lo, *qhi, *qlo, *khi, *klo, *vhi, *vlo, *chi, *clo;
    bf16 *fhi, *flo, *phi, *plo, *awhi, *awlo, *f1hi, *f1lo, *f2hi, *f2lo;
    cudaGetSymbolAddress((void**)&h,    g_h);
    cudaGetSymbolAddress((void**)&sc,   g_sc);
    cudaGetSymbolAddress((void**)&o1,   g_o1);
    cudaGetSymbolAddress((void**)&o2,   g_o2);
    cudaGetSymbolAddress((void**)&h2hi, g_h2hi);
    cudaGetSymbolAddress((void**)&h2lo, g_h2lo);
    cudaGetSymbolAddress((void**)&qhi,  g_qhi);
    cudaGetSymbolAddress((void**)&qlo,  g_qlo);
    cudaGetSymbolAddress((void**)&khi,  g_khi);
    cudaGetSymbolAddress((void**)&klo,  g_klo);
    cudaGetSymbolAddress((void**)&vhi,  g_vhi);
    cudaGetSymbolAddress((void**)&vlo,  g_vlo);
    cudaGetSymbolAddress((void**)&chi,  g_chi);
    cudaGetSymbolAddress((void**)&clo,  g_clo);
    cudaGetSymbolAddress((void**)&fhi,  g_fhi);
    cudaGetSymbolAddress((void**)&flo,  g_flo);
    cudaGetSymbolAddress((void**)&phi,  g_phi);
    cudaGetSymbolAddress((void**)&plo,  g_plo);
    cudaGetSymbolAddress((void**)&awhi, g_awhi);
    cudaGetSymbolAddress((void**)&awlo, g_awlo);
    cudaGetSymbolAddress((void**)&f1hi, g_f1hi);
    cudaGetSymbolAddress((void**)&f1lo, g_f1lo);
    cudaGetSymbolAddress((void**)&f2hi, g_f2hi);
    cudaGetSymbolAddress((void**)&f2lo, g_f2lo);

    cudaFuncSetAttribute(wgemm_kernel<false,false,true>,
                         cudaFuncAttributeMaxDynamicSharedMemorySize, SM_NN);
    cudaFuncSetAttribute(wgemm_kernel<true,false,true>,
                         cudaFuncAttributeMaxDynamicSharedMemorySize, SM_NN);
    cudaFuncSetAttribute(wgemm_kernel<false,true,false>,
                         cudaFuncAttributeMaxDynamicSharedMemorySize, SM_NN);
    cudaFuncSetAttribute(scores_mma,
                         cudaFuncAttributeMaxDynamicSharedMemorySize, SM_NT);
    cudaFuncSetAttribute(attnv_mma,
                         cudaFuncAttributeMaxDynamicSharedMemorySize, SM_NN);

    const int M = Bk * Sk;           // 8192
    const int* masks[3] = { dmask, smask, gmask };

    // one-time (per launch) weight splits — layout preserved [K][N]
    wsplit_kernel<<<(Lk*3*4*Dk*Dk) / 1024, 256>>>(attn_w, awhi, awlo);
    wsplit_kernel<<<(Lk*Dk*FFk) / 1024, 256>>>(ff_w1, f1hi, f1lo);
    wsplit_kernel<<<(Lk*FFk*Dk) / 1024, 256>>>(ff_w2, f2hi, f2lo);

    input_proj_kernel<<<M, Dk>>>(x, cond, in_w, in_b, cond_w, cond_b, h);

    for (int l = 0; l < Lk; l++) {
        inorm_kernel<<<M, 256>>>(h, h2hi, h2lo);
        for (int brn = 0; brn < 3; brn++) {
            const size_t wb = (((size_t)l * 3 + brn) * 4) * Dk * Dk;
            const size_t bb = (((size_t)l * 3 + brn) * 4) * Dk;
            const float* Bb = attn_b + bb;
            wgemm_kernel<false,false,true><<<dim3(4, 64), 256, SM_NN>>>(
                h2hi, h2lo, awhi + wb,            awlo + wb,            Bb,        nullptr, qhi, qlo, M, Dk, Dk);
            wgemm_kernel<false,false,true><<<dim3(4, 64), 256, SM_NN>>>(
                h2hi, h2lo, awhi + wb + 1*Dk*Dk,  awlo + wb + 1*Dk*Dk,  Bb + Dk,   nullptr, khi, klo, M, Dk, Dk);
            wgemm_kernel<false,false,true><<<dim3(4, 64), 256, SM_NN>>>(
                h2hi, h2lo, awhi + wb + 2*Dk*Dk,  awlo + wb + 2*Dk*Dk,  Bb + 2*Dk, nullptr, vhi, vlo, M, Dk, Dk);
            scores_mma<<<dim3(4, 4, Bk*Hh), 256, SM_NT>>>(qhi, qlo, khi, klo, masks[brn], sc);
            softmax_kernel<<<Bk*Hh*Sk, 256>>>(sc, phi, plo);
            attnv_mma<<<dim3(1, 4, Bk*Hh), 256, SM_NN>>>(phi, plo, vhi, vlo, chi, clo);
            wgemm_kernel<false,true,false><<<dim3(4, 64), 256, SM_NN>>>(
                chi, clo, awhi + wb + 3*Dk*Dk,    awlo + wb + 3*Dk*Dk,  Bb + 3*Dk, h, nullptr, nullptr, M, Dk, Dk);
        }
        inorm_kernel<<<M, 256>>>(h, h2hi, h2lo);
        wgemm_kernel<true,false,true><<<dim3(8, 64), 256, SM_NN>>>(
            h2hi, h2lo, f1hi + (size_t)l*Dk*FFk, f1lo + (size_t)l*Dk*FFk,
            ff_b1 + (size_t)l*FFk, nullptr, fhi, flo, M, FFk, Dk);
        wgemm_kernel<false,true,false><<<dim3(4, 64), 256, SM_NN>>>(
            fhi, flo, f2hi + (size_t)l*FFk*Dk, f2lo + (size_t)l*FFk*Dk,
            ff_b2 + (size_t)l*Dk, h, nullptr, nullptr, M, Dk, FFk);
    }

    sgemm_kernel<true, true, false><<<dim3(4, 64), 256>>>(h,  out1_w, out1_b, o1, M, Dk,   Dk);
    sgemm_kernel<true, true, false><<<dim3(2, 64), 256>>>(o1, out2_w, out2_b, o2, M, Dk/2, Dk);
    out3_kernel<<<(M * 2 + 255) / 256, 256>>>(o2, out3_w, out3_b, (float*)d_out);
}

// round 4
// speedup vs baseline: 2.4145x; 1.0326x over previous
#include <cuda_runtime.h>
#include <cuda_bf16.h>
#include <cstdint>
#include <math.h>

#define Bk 16
#define Sk 512
#define Dk 512
#define Hh 4
#define DKk 128
#define FFk 1024
#define Lk 4

typedef __nv_bfloat16 bf16;
typedef __nv_bfloat162 bf162;

// ==================== scratch (device globals; no allocation) ===============
__device__ float g_h  [Bk*Sk*Dk];
__device__ float g_sc [(size_t)Bk*Hh*Sk*Sk];
__device__ float g_o2 [Bk*Sk*(Dk/2)];
// bf16 hi/lo activation splits
__device__ bf16 g_h2hi[Bk*Sk*Dk],  g_h2lo[Bk*Sk*Dk];
__device__ bf16 g_qkvhi[(size_t)Bk*Sk*3*Dk], g_qkvlo[(size_t)Bk*Sk*3*Dk];
__device__ bf16 g_chi [Bk*Sk*Dk],  g_clo [Bk*Sk*Dk];
__device__ bf16 g_fhi [Bk*Sk*FFk], g_flo [Bk*Sk*FFk];
__device__ bf16 g_phi [(size_t)Bk*Hh*Sk*Sk], g_plo [(size_t)Bk*Hh*Sk*Sk];
// bf16 hi/lo weight splits
__device__ bf16 g_awhi[(size_t)Lk*3*4*Dk*Dk], g_awlo[(size_t)Lk*3*4*Dk*Dk];  // out-proj slice used
__device__ bf16 g_qkvwhi[(size_t)Lk*3*Dk*3*Dk], g_qkvwlo[(size_t)Lk*3*Dk*3*Dk]; // packed [512][1536]
__device__ float g_qkvb[(size_t)Lk*3*3*Dk];
__device__ bf16 g_f1hi[(size_t)Lk*Dk*FFk],    g_f1lo[(size_t)Lk*Dk*FFk];
__device__ bf16 g_f2hi[(size_t)Lk*FFk*Dk],    g_f2lo[(size_t)Lk*FFk*Dk];
__device__ bf16 g_o1whi[Dk*Dk],     g_o1wlo[Dk*Dk];
__device__ bf16 g_o2whi[Dk*(Dk/2)], g_o2wlo[Dk*(Dk/2)];

// ==================== low-level helpers =====================================
__device__ __forceinline__ uint32_t smem_u32(const void* p) {
    return (uint32_t)__cvta_generic_to_shared(p);
}
__device__ __forceinline__ void ldsm4(uint32_t* r, uint32_t addr) {
    asm volatile("ldmatrix.sync.aligned.m8n8.x4.shared.b16 {%0,%1,%2,%3}, [%4];"
        : "=r"(r[0]), "=r"(r[1]), "=r"(r[2]), "=r"(r[3]) : "r"(addr));
}
__device__ __forceinline__ void ldsm4t(uint32_t* r, uint32_t addr) {
    asm volatile("ldmatrix.sync.aligned.m8n8.x4.trans.shared.b16 {%0,%1,%2,%3}, [%4];"
        : "=r"(r[0]), "=r"(r[1]), "=r"(r[2]), "=r"(r[3]) : "r"(addr));
}
__device__ __forceinline__ void mma_bf16(float* c, const uint32_t* a,
                                         uint32_t b0, uint32_t b1) {
    asm volatile("mma.sync.aligned.m16n8k16.row.col.f32.bf16.bf16.f32 "
        "{%0,%1,%2,%3},{%4,%5,%6,%7},{%8,%9},{%0,%1,%2,%3};"
        : "+f"(c[0]), "+f"(c[1]), "+f"(c[2]), "+f"(c[3])
        : "r"(a[0]), "r"(a[1]), "r"(a[2]), "r"(a[3]), "r"(b0), "r"(b1));
}
__device__ __forceinline__ void cp16(uint32_t saddr, const bf16* g) {
    asm volatile("cp.async.cg.shared.global [%0], [%1], 16;"
        :: "r"(saddr), "l"(__cvta_generic_to_global(g)) : "memory");
}
#define CP_COMMIT()   asm volatile("cp.async.commit_group;" ::: "memory")
#define CP_WAIT(n)    asm volatile("cp.async.wait_group %0;" :: "n"(n) : "memory")

__device__ __forceinline__ void split_store2(bf16* hi, bf16* lo, size_t off,
                                             float x, float y) {
    bf16 hx = __float2bfloat16_rn(x);
    bf16 hy = __float2bfloat16_rn(y);
    bf162 hv; hv.x = hx; hv.y = hy;
    *(bf162*)(hi + off) = hv;
    bf162 lv;
    lv.x = __float2bfloat16_rn(x - __bfloat162float(hx));
    lv.y = __float2bfloat16_rn(y - __bfloat162float(hy));
    *(bf162*)(lo + off) = lv;
}

// ==================== smem tile loaders =====================================
// A-style tile: 128 rows x 32 bf16, row pitch 80B (conflict-free skew)
#define TA_BYTES 10240
__device__ __forceinline__ void cpA(uint32_t sbase, const bf16* g, int ld, int tid) {
    #pragma unroll
    for (int i = 0; i < 2; i++) {
        int idx = tid + i * 256;
        int r = idx >> 2, c = idx & 3;
        cp16(sbase + (uint32_t)(r * 80 + c * 16), g + (size_t)r * ld + c * 8);
    }
}
// B NN-style tile: 32 rows (k) x 128 bf16 (n), pitch 256B, XOR swizzle
#define TB_BYTES 8192
__device__ __forceinline__ void cpB_nn(uint32_t sbase, const bf16* g, int ld, int tid) {
    #pragma unroll
    for (int i = 0; i < 2; i++) {
        int idx = tid + i * 256;
        int k = idx >> 4, c = idx & 15;
        cp16(sbase + (uint32_t)(k * 256 + ((c ^ (k & 7)) << 4)),
             g + (size_t)k * ld + c * 8);
    }
}

// ==================== bf16x3 compute core ===================================
template<bool NNB>
__device__ __forceinline__ void compute_stage(uint32_t aHi, uint32_t aLo,
        uint32_t bHi, uint32_t bLo, int wm, int wn, int lane, float acc[2][8][4])
{
    #pragma unroll
    for (int s = 0; s < 2; s++) {
        uint32_t ah[2][4], al[2][4], bh[4][4], bl[4][4];
        uint32_t aoff = (uint32_t)((wm + (lane & 15)) * 80 + (s * 2 + (lane >> 4)) * 16);
        ldsm4(ah[0], aHi + aoff);
        ldsm4(ah[1], aHi + aoff + 16 * 80);
        ldsm4(al[0], aLo + aoff);
        ldsm4(al[1], aLo + aoff + 16 * 80);
        if (NNB) {
            int k  = s * 16 + (lane & 7) + ((lane >> 3) & 1) * 8;
            int cb = (wn >> 3) + (lane >> 4);
            uint32_t ro = (uint32_t)(k * 256);
            #pragma unroll
            for (int t = 0; t < 4; t++) {
                uint32_t off = ro + (uint32_t)(((cb + t * 2) ^ (k & 7)) << 4);
                ldsm4t(bh[t], bHi + off);
            }
        } else {
            uint32_t boff = (uint32_t)((wn + (lane & 15)) * 80 + (s * 2 + (lane >> 4)) * 16);
            #pragma unroll
            for (int t = 0; t < 4; t++)
                ldsm4(bh[t], bHi + boff + t * 16 * 80);
        }
        #pragma unroll
        for (int mt = 0; mt < 2; mt++)
            #pragma unroll
            for (int j = 0; j < 8; j++) {
                int t = j >> 1, o = j & 1;
                uint32_t b0, b1;
                if (NNB) { b0 = bh[t][o * 2]; b1 = bh[t][o * 2 + 1]; }
                else     { b0 = bh[t][o];     b1 = bh[t][o + 2];     }
                mma_bf16(acc[mt][j], ah[mt], b0, b1);
                mma_bf16(acc[mt][j], al[mt], b0, b1);
            }
        if (NNB) {
            int k  = s * 16 + (lane & 7) + ((lane >> 3) & 1) * 8;
            int cb = (wn >> 3) + (lane >> 4);
            uint32_t ro = (uint32_t)(k * 256);
            #pragma unroll
            for (int t = 0; t < 4; t++) {
                uint32_t off = ro + (uint32_t)(((cb + t * 2) ^ (k & 7)) << 4);
                ldsm4t(bl[t], bLo + off);
            }
        } else {
            uint32_t boff = (uint32_t)((wn + (lane & 15)) * 80 + (s * 2 + (lane >> 4)) * 16);
            #pragma unroll
            for (int t = 0; t < 4; t++)
                ldsm4(bl[t], bLo + boff + t * 16 * 80);
        }
        #pragma unroll
        for (int mt = 0; mt < 2; mt++)
            #pragma unroll
            for (int j = 0; j < 8; j++) {
                int t = j >> 1, o = j & 1;
                uint32_t b0, b1;
                if (NNB) { b0 = bl[t][o * 2]; b1 = bl[t][o * 2 + 1]; }
                else     { b0 = bl[t][o];     b1 = bl[t][o + 2];     }
                mma_bf16(acc[mt][j], ah[mt], b0, b1);
            }
    }
}

// ==================== wgemm: C[M,N] (+)= A[M,K] @ B[K,N], 3-stage ring ======
#define ST_NN   (2 * TA_BYTES + 2 * TB_BYTES)   // 36864
#define SM_NN3  (3 * ST_NN)                     // 110592
template<bool RELU, bool ACCUM, bool OUTSPLIT>
__global__ void __launch_bounds__(256, 2)
wgemm_kernel(const bf16* __restrict__ Ahi, const bf16* __restrict__ Alo,
             const bf16* __restrict__ Bhi, const bf16* __restrict__ Blo,
             const float* __restrict__ bias,
             float* __restrict__ C, bf16* __restrict__ Chi, bf16* __restrict__ Clo,
             int M, int N, int K)
{
    extern __shared__ __align__(128) char smem[];
    const uint32_t sb = smem_u32(smem);
    const int tid = threadIdx.x, lane = tid & 31, w = tid >> 5;
    const int wm = (w & 3) * 32, wn = (w >> 2) * 64;
    const int bm = blockIdx.y * 128, bn = blockIdx.x * 128;
    const int NC = K >> 5;

    float acc[2][8][4];
    #pragma unroll
    for (int i = 0; i < 2; i++)
        #pragma unroll
        for (int j = 0; j < 8; j++)
            #pragma unroll
            for (int q = 0; q < 4; q++) acc[i][j][q] = 0.f;

    const bf16* Agh = Ahi + (size_t)bm * K;
    const bf16* Agl = Alo + (size_t)bm * K;
    const bf16* Bgh = Bhi + bn;
    const bf16* Bgl = Blo + bn;

    auto load = [&](int c, int stg) {
        uint32_t s0 = sb + stg * ST_NN;
        cpA   (s0,                 Agh + c * 32, K, tid);
        cpA   (s0 + TA_BYTES,      Agl + c * 32, K, tid);
        cpB_nn(s0 + 2 * TA_BYTES,            Bgh + (size_t)(c * 32) * N, N, tid);
        cpB_nn(s0 + 2 * TA_BYTES + TB_BYTES, Bgl + (size_t)(c * 32) * N, N, tid);
        CP_COMMIT();
    };

    load(0, 0);
    load(1, 1);
    int stg = 0;
    for (int c = 0; c < NC; c++) {
        if (c + 1 < NC) { CP_WAIT(1); } else { CP_WAIT(0); }
        __syncthreads();
        if (c + 2 < NC) load(c + 2, (stg + 2 > 2) ? stg - 1 : stg + 2);
        uint32_t s0 = sb + stg * ST_NN;
        compute_stage<true>(s0, s0 + TA_BYTES, s0 + 2 * TA_BYTES,
                            s0 + 2 * TA_BYTES + TB_BYTES, wm, wn, lane, acc);
        stg = (stg == 2) ? 0 : stg + 1;
    }

    #pragma unroll
    for (int mt = 0; mt < 2; mt++) {
        int r0 = bm + wm + mt * 16 + (lane >> 2);
        #pragma unroll
        for (int j = 0; j < 8; j++) {
            int col = bn + wn + j * 8 + (lane & 3) * 2;
            float b0 = bias[col], b1 = bias[col + 1];
            float v00 = acc[mt][j][0] + b0, v01 = acc[mt][j][1] + b1;
            float v10 = acc[mt][j][2] + b0, v11 = acc[mt][j][3] + b1;
            size_t o0 = (size_t)r0 * N + col;
            size_t o1 = (size_t)(r0 + 8) * N + col;
            if (ACCUM) {
                float2 c0 = *(const float2*)(C + o0);
                float2 c1 = *(const float2*)(C + o1);
                v00 += c0.x; v01 += c0.y; v10 += c1.x; v11 += c1.y;
            }
            if (RELU) {
                v00 = fmaxf(v00, 0.f); v01 = fmaxf(v01, 0.f);
                v10 = fmaxf(v10, 0.f); v11 = fmaxf(v11, 0.f);
            }
            if (OUTSPLIT) {
                split_store2(Chi, Clo, o0, v00, v01);
                split_store2(Chi, Clo, o1, v10, v11);
            } else {
                float2 r; r.x = v00; r.y = v01; *(float2*)(C + o0) = r;
                float2 s; s.x = v10; s.y = v11; *(float2*)(C + o1) = s;
            }
        }
    }
}

// ==================== scores: sc = mask ? -1e9 : (Q@K^T)*scale ==============
#define ST_NT   (4 * TA_BYTES)      // 40960
#define SM_NT   (2 * ST_NT)         // 81920
__global__ void __launch_bounds__(256, 2)
scores_mma(const bf16* __restrict__ qkvhi, const bf16* __restrict__ qkvlo,
           const int* __restrict__ mask, float* __restrict__ sc)
{
    extern __shared__ __align__(128) char smem[];
    const uint32_t sb = smem_u32(smem);
    const int tid = threadIdx.x, lane = tid & 31, w = tid >> 5;
    const int wm = (w & 3) * 32, wn = (w >> 2) * 64;
    const int z = blockIdx.z, b = z >> 2, h = z & 3;
    const int bm = blockIdx.y * 128, bn = blockIdx.x * 128;
    const int LD = 3 * Dk;
    const size_t qb = (size_t)b * Sk * LD + h * DKk;          // q section
    const size_t kb = qb + Dk;                                 // k section

    float acc[2][8][4];
    #pragma unroll
    for (int i = 0; i < 2; i++)
        #pragma unroll
        for (int j = 0; j < 8; j++)
            #pragma unroll
            for (int q = 0; q < 4; q++) acc[i][j][q] = 0.f;

    const bf16* Qh = qkvhi + qb + (size_t)bm * LD;
    const bf16* Ql = qkvlo + qb + (size_t)bm * LD;
    const bf16* Kh = qkvhi + kb + (size_t)bn * LD;
    const bf16* Kl = qkvlo + kb + (size_t)bn * LD;

    auto load = [&](int c, int stg2) {
        uint32_t s0 = sb + stg2 * ST_NT;
        cpA(s0,                Qh + c * 32, LD, tid);
        cpA(s0 + TA_BYTES,     Ql + c * 32, LD, tid);
        cpA(s0 + 2 * TA_BYTES, Kh + c * 32, LD, tid);
        cpA(s0 + 3 * TA_BYTES, Kl + c * 32, LD, tid);
        CP_COMMIT();
    };

    load(0, 0);
    const int NC = DKk >> 5;   // 4
    for (int c = 0; c < NC; c++) {
        if (c + 1 < NC) { load(c + 1, (c + 1) & 1); CP_WAIT(1); }
        else            { CP_WAIT(0); }
        __syncthreads();
        uint32_t s0 = sb + (c & 1) * ST_NT;
        compute_stage<false>(s0, s0 + TA_BYTES, s0 + 2 * TA_BYTES,
                             s0 + 3 * TA_BYTES, wm, wn, lane, acc);
        __syncthreads();
    }

    const float scale = 0.08838834764831845f;  // 1/sqrt(128)
    float* sp = sc + (size_t)z * Sk * Sk;
    const int* mp = mask + (size_t)b * Sk * Sk;
    #pragma unroll
    for (int mt = 0; mt < 2; mt++) {
        int r0 = bm + wm + mt * 16 + (lane >> 2);
        #pragma unroll
        for (int j = 0; j < 8; j++) {
            int col = bn + wn + j * 8 + (lane & 3) * 2;
            size_t o0 = (size_t)r0 * Sk + col;
            size_t o1 = (size_t)(r0 + 8) * Sk + col;
            int2 m0 = *(const int2*)(mp + o0);
            int2 m1 = *(const int2*)(mp + o1);
            float2 r, s;
            r.x = m0.x ? -1e9f : acc[mt][j][0] * scale;
            r.y = m0.y ? -1e9f : acc[mt][j][1] * scale;
            s.x = m1.x ? -1e9f : acc[mt][j][2] * scale;
            s.y = m1.y ? -1e9f : acc[mt][j][3] * scale;
            *(float2*)(sp + o0) = r;
            *(float2*)(sp + o1) = s;
        }
    }
}

// ==================== attnv: ctx = P @ V, 3-stage ring ======================
__global__ void __launch_bounds__(256, 2)
attnv_mma(const bf16* __restrict__ phi, const bf16* __restrict__ plo,
          const bf16* __restrict__ qkvhi, const bf16* __restrict__ qkvlo,
          bf16* __restrict__ chi, bf16* __restrict__ clo)
{
    extern __shared__ __align__(128) char smem[];
    const uint32_t sb = smem_u32(smem);
    const int tid = threadIdx.x, lane = tid & 31, w = tid >> 5;
    const int wm = (w & 3) * 32, wn = (w >> 2) * 64;
    const int z = blockIdx.z, b = z >> 2, h = z & 3;
    const int bm = blockIdx.y * 128;
    const int LD = 3 * Dk;
    const size_t vb = (size_t)b * Sk * LD + 2 * Dk + h * DKk;  // v section
    const size_t cb = (size_t)b * Sk * Dk + h * DKk;

    float acc[2][8][4];
    #pragma unroll
    for (int i = 0; i < 2; i++)
        #pragma unroll
        for (int j = 0; j < 8; j++)
            #pragma unroll
            for (int q = 0; q < 4; q++) acc[i][j][q] = 0.f;

    const bf16* Ph = phi + (size_t)z * Sk * Sk + (size_t)bm * Sk;
    const bf16* Pl = plo + (size_t)z * Sk * Sk + (size_t)bm * Sk;
    const bf16* Vh = qkvhi + vb;
    const bf16* Vl = qkvlo + vb;

    auto load = [&](int c, int stg2) {
        uint32_t s0 = sb + stg2 * ST_NN;
        cpA   (s0,                 Ph + c * 32, Sk, tid);
        cpA   (s0 + TA_BYTES,      Pl + c * 32, Sk, tid);
        cpB_nn(s0 + 2 * TA_BYTES,            Vh + (size_t)(c * 32) * LD, LD, tid);
        cpB_nn(s0 + 2 * TA_BYTES + TB_BYTES, Vl + (size_t)(c * 32) * LD, LD, tid);
        CP_COMMIT();
    };

    load(0, 0);
    load(1, 1);
    const int NC = Sk >> 5;  // 16
    int stg = 0;
    for (int c = 0; c < NC; c++) {
        if (c + 1 < NC) { CP_WAIT(1); } else { CP_WAIT(0); }
        __syncthreads();
        if (c + 2 < NC) load(c + 2, (stg + 2 > 2) ? stg - 1 : stg + 2);
        uint32_t s0 = sb + stg * ST_NN;
        compute_stage<true>(s0, s0 + TA_BYTES, s0 + 2 * TA_BYTES,
                            s0 + 2 * TA_BYTES + TB_BYTES, wm, wn, lane, acc);
        stg = (stg == 2) ? 0 : stg + 1;
    }

    bf16* ch = chi + cb;
    bf16* cl = clo + cb;
    #pragma unroll
    for (int mt = 0; mt < 2; mt++) {
        int r0 = bm + wm + mt * 16 + (lane >> 2);
        #pragma unroll
        for (int j = 0; j < 8; j++) {
            int col = wn + j * 8 + (lane & 3) * 2;   // 0..127 within head
            size_t o0 = (size_t)r0 * Dk + col;
            size_t o1 = (size_t)(r0 + 8) * Dk + col;
            split_store2(ch, cl, o0, acc[mt][j][0], acc[mt][j][1]);
            split_store2(ch, cl, o1, acc[mt][j][2], acc[mt][j][3]);
        }
    }
}

// ==================== weight split / pack kernels ===========================
__global__ void wsplit_kernel(const float* __restrict__ w, bf16* __restrict__ hi,
                              bf16* __restrict__ lo)
{
    int i = (blockIdx.x * 256 + threadIdx.x) * 4;
    float4 v = *(const float4*)(w + i);
    split_store2(hi, lo, i,     v.x, v.y);
    split_store2(hi, lo, i + 2, v.z, v.w);
}

__global__ void split_kernel(const float* __restrict__ x, bf16* __restrict__ hi,
                             bf16* __restrict__ lo)
{
    int i = (blockIdx.x * 256 + threadIdx.x) * 4;
    float4 v = *(const float4*)(x + i);
    split_store2(hi, lo, i,     v.x, v.y);
    split_store2(hi, lo, i + 2, v.z, v.w);
}

// attn_w [L,3,4,512,512] -> packed qkv [L*3][512][1536] (q|k|v columns)
__global__ void pack_qkv_kernel(const float* __restrict__ aw,
                                bf16* __restrict__ hi, bf16* __restrict__ lo)
{
    size_t o = ((size_t)blockIdx.x * 256 + threadIdx.x) * 2;
    size_t lb = o / ((size_t)Dk * 3 * Dk);
    size_t r  = o % ((size_t)Dk * 3 * Dk);
    int k = (int)(r / (3 * Dk));
    int c = (int)(r % (3 * Dk));
    int j = c >> 9, n = c & 511;
    const float* src = aw + (((lb * 4 + j) * Dk + k) * Dk + n);
    float2 v = *(const float2*)src;
    split_store2(hi, lo, o, v.x, v.y);
}

__global__ void pack_qkvb_kernel(const float* __restrict__ ab, float* __restrict__ out)
{
    int o = blockIdx.x * 256 + threadIdx.x;   // < Lk*3*1536
    int lb = o / 1536, c = o % 1536;
    int j = c >> 9, n = c & 511;
    out[o] = ab[((lb * 4 + j) * Dk) + n];
}

// ==================== reductions ============================================
__device__ __forceinline__ float warpReduceSum(float v) {
    #pragma unroll
    for (int o = 16; o > 0; o >>= 1) v += __shfl_xor_sync(0xffffffffu, v, o);
    return v;
}
__device__ __forceinline__ float warpReduceMax(float v) {
    #pragma unroll
    for (int o = 16; o > 0; o >>= 1) v = fmaxf(v, __shfl_xor_sync(0xffffffffu, v, o));
    return v;
}

// ==================== input projection (4 outputs/thread) ===================
__global__ void input_proj_kernel(const float* __restrict__ x,
                                  const float* __restrict__ cond,
                                  const float* __restrict__ in_w,
                                  const float* __restrict__ in_b,
                                  const float* __restrict__ cond_w,
                                  const float* __restrict__ cond_b,
                                  float* __restrict__ h)
{
    __shared__ float xs[2][18];
    __shared__ float cs[2][89];
    int tok0 = blockIdx.x * 2;
    int t = threadIdx.x;          // 256
    if (t < 36)  xs[t / 18][t % 18] = x[(size_t)tok0 * 18 + t];
    if (t < 178) cs[t / 89][t % 89] = cond[(size_t)tok0 * 89 + t];
    __syncthreads();
    int half = t >> 7, lt = t & 127;
    int col = lt * 4;
    float4 ib = *(const float4*)(in_b + col);
    float4 cbv = *(const float4*)(cond_b + col);
    float a0 = ib.x + cbv.x, a1 = ib.y + cbv.y, a2 = ib.z + cbv.z, a3 = ib.w + cbv.w;
    #pragma unroll 3
    for (int k = 0; k < 18; k++) {
        float4 wv = *(const float4*)(in_w + k * Dk + col);
        float xv = xs[half][k];
        a0 = fmaf(xv, wv.x, a0); a1 = fmaf(xv, wv.y, a1);
        a2 = fmaf(xv, wv.z, a2); a3 = fmaf(xv, wv.w, a3);
    }
    #pragma unroll 3
    for (int k = 0; k < 89; k++) {
        float4 wv = *(const float4*)(cond_w + k * Dk + col);
        float cv = cs[half][k];
        a0 = fmaf(cv, wv.x, a0); a1 = fmaf(cv, wv.y, a1);
        a2 = fmaf(cv, wv.z, a2); a3 = fmaf(cv, wv.w, a3);
    }
    float4 r; r.x = a0; r.y = a1; r.z = a2; r.w = a3;
    *(float4*)(h + (size_t)(tok0 + half) * Dk + col) = r;
}

// ==================== instance norm (writes bf16 hi/lo split) ===============
__global__ void inorm_kernel(const float* __restrict__ x,
                             bf16* __restrict__ yhi, bf16* __restrict__ ylo)
{
    __shared__ float s1[8], s2[8];
    const size_t base = (size_t)blockIdx.x * Dk;
    int t = threadIdx.x;          // 256
    float a = x[base + t], b = x[base + t + 256];
    float sum = warpReduceSum(a + b);
    float sq  = warpReduceSum(a * a + b * b);
    if ((t & 31) == 0) { s1[t >> 5] = sum; s2[t >> 5] = sq; }
    __syncthreads();
    if (t < 32) {
        float v1 = (t < 8) ? s1[t] : 0.f;
        float v2 = (t < 8) ? s2[t] : 0.f;
        v1 = warpReduceSum(v1);
        v2 = warpReduceSum(v2);
        if (t == 0) { s1[0] = v1; s2[0] = v2; }
    }
    __syncthreads();
    float mean = s1[0] * (1.f / Dk);
    float var  = s2[0] * (1.f / Dk) - mean * mean;
    float r = rsqrtf(var + 1e-5f);
    float y0 = (a - mean) * r, y1 = (b - mean) * r;
    bf16 h0 = __float2bfloat16_rn(y0);
    bf16 h1 = __float2bfloat16_rn(y1);
    yhi[base + t]       = h0;
    yhi[base + t + 256] = h1;
    ylo[base + t]       = __float2bfloat16_rn(y0 - __bfloat162float(h0));
    ylo[base + t + 256] = __float2bfloat16_rn(y1 - __bfloat162float(h1));
}

// ==================== softmax (fp32 in, bf16 hi/lo out) =====================
__global__ void softmax_kernel(const float* __restrict__ scores,
                               bf16* __restrict__ phi, bf16* __restrict__ plo)
{
    __shared__ float red[8];
    const float* row = scores + (size_t)blockIdx.x * Sk;
    const size_t base = (size_t)blockIdx.x * Sk;
    int t = threadIdx.x;  // 256
    float v0 = row[t], v1 = row[t + 256];
    float m = warpReduceMax(fmaxf(v0, v1));
    if ((t & 31) == 0) red[t >> 5] = m;
    __syncthreads();
    if (t < 32) {
        float mm = (t < 8) ? red[t] : -3.4e38f;
        mm = warpReduceMax(mm);
        if (t == 0) red[0] = mm;
    }
    __syncthreads();
    m = red[0];
    __syncthreads();
    float e0 = __expf(v0 - m), e1 = __expf(v1 - m);
    float s = warpReduceSum(e0 + e1);
    if ((t & 31) == 0) red[t >> 5] = s;
    __syncthreads();
    if (t < 32) {
        float ss = (t < 8) ? red[t] : 0.f;
        ss = warpReduceSum(ss);
        if (t == 0) red[0] = ss;
    }
    __syncthreads();
    float inv = 1.f / red[0];
    float p0 = e0 * inv, p1 = e1 * inv;
    bf16 h0 = __float2bfloat16_rn(p0);
    bf16 h1 = __float2bfloat16_rn(p1);
    phi[base + t]       = h0;
    phi[base + t + 256] = h1;
    plo[base + t]       = __float2bfloat16_rn(p0 - __bfloat162float(h0));
    plo[base + t + 256] = __float2bfloat16_rn(p1 - __bfloat162float(h1));
}

// ==================== final tiny head =======================================
__global__ void out3_kernel(const float* __restrict__ o2,
                            const float* __restrict__ w,
                            const float* __restrict__ b,
                            float* __restrict__ out)
{
    int idx = blockIdx.x * 256 + threadIdx.x;
    if (idx >= Bk * Sk * 2) return;
    int tok = idx >> 1, j = idx & 1;
    const float* o = o2 + (size_t)tok * 256;
    float acc = b[j];
    #pragma unroll 8
    for (int kk = 0; kk < 256; kk++) acc = fmaf(o[kk], w[kk * 2 + j], acc);
    out[idx] = acc;
}

// ============================ host launcher =================================
extern "C" void kernel_launch(void* const* d_in, const int* in_sizes, int n_in,
                              void* d_out, int out_size)
{
    const float* x      = (const float*)d_in[0];
    const float* cond   = (const float*)d_in[1];
    const int*   dmask  = (const int*)  d_in[2];
    const int*   smask  = (const int*)  d_in[3];
    const int*   gmask  = (const int*)  d_in[4];
    const float* attn_w = (const float*)d_in[5];
    const float* attn_b = (const float*)d_in[6];
    const float* ff_w1  = (const float*)d_in[7];
    const float* ff_b1  = (const float*)d_in[8];
    const float* ff_w2  = (const float*)d_in[9];
    const float* ff_b2  = (const float*)d_in[10];
    const float* in_w   = (const float*)d_in[11];
    const float* in_b   = (const float*)d_in[12];
    const float* cond_w = (const float*)d_in[13];
    const float* cond_b = (const float*)d_in[14];
    const float* out1_w = (const float*)d_in[15];
    const float* out1_b = (const float*)d_in[16];
    const float* out2_w = (const float*)d_in[17];
    const float* out2_b = (const float*)d_in[18];
    const float* out3_w = (const float*)d_in[19];
    const float* out3_b = (const float*)d_in[20];

    float *h, *sc, *o2, *qkvb;
    bf16 *h2hi, *h2lo, *qkvhi, *qkvlo, *chi, *clo, *fhi, *flo, *phi, *plo;
    bf16 *awhi, *awlo, *qkvwhi, *qkvwlo, *f1hi, *f1lo, *f2hi, *f2lo;
    bf16 *o1whi, *o1wlo, *o2whi, *o2wlo;
    cudaGetSymbolAddress((void**)&h,     g_h);
    cudaGetSymbolAddress((void**)&sc,    g_sc);
    cudaGetSymbolAddress((void**)&o2,    g_o2);
    cudaGetSymbolAddress((void**)&qkvb,  g_qkvb);
    cudaGetSymbolAddress((void**)&h2hi,  g_h2hi);
    cudaGetSymbolAddress((void**)&h2lo,  g_h2lo);
    cudaGetSymbolAddress((void**)&qkvhi, g_qkvhi);
    cudaGetSymbolAddress((void**)&qkvlo, g_qkvlo);
    cudaGetSymbolAddress((void**)&chi,   g_chi);
    cudaGetSymbolAddress((void**)&clo,   g_clo);
    cudaGetSymbolAddress((void**)&fhi,   g_fhi);
    cudaGetSymbolAddress((void**)&flo,   g_flo);
    cudaGetSymbolAddress((void**)&phi,   g_phi);
    cudaGetSymbolAddress((void**)&plo,   g_plo);
    cudaGetSymbolAddress((void**)&awhi,  g_awhi);
    cudaGetSymbolAddress((void**)&awlo,  g_awlo);
    cudaGetSymbolAddress((void**)&qkvwhi, g_qkvwhi);
    cudaGetSymbolAddress((void**)&qkvwlo, g_qkvwlo);
    cudaGetSymbolAddress((void**)&f1hi,  g_f1hi);
    cudaGetSymbolAddress((void**)&f1lo,  g_f1lo);
    cudaGetSymbolAddress((void**)&f2hi,  g_f2hi);
    cudaGetSymbolAddress((void**)&f2lo,  g_f2lo);
    cudaGetSymbolAddress((void**)&o1whi, g_o1whi);
    cudaGetSymbolAddress((void**)&o1wlo, g_o1wlo);
    cudaGetSymbolAddress((void**)&o2whi, g_o2whi);
    cudaGetSymbolAddress((void**)&o2wlo, g_o2wlo);

    cudaFuncSetAttribute(wgemm_kernel<false,false,true>,
                         cudaFuncAttributeMaxDynamicSharedMemorySize, SM_NN3);
    cudaFuncSetAttribute(wgemm_kernel<true,false,true>,
                         cudaFuncAttributeMaxDynamicSharedMemorySize, SM_NN3);
    cudaFuncSetAttribute(wgemm_kernel<false,true,false>,
                         cudaFuncAttributeMaxDynamicSharedMemorySize, SM_NN3);
    cudaFuncSetAttribute(wgemm_kernel<true,false,false>,
                         cudaFuncAttributeMaxDynamicSharedMemorySize, SM_NN3);
    cudaFuncSetAttribute(scores_mma,
                         cudaFuncAttributeMaxDynamicSharedMemorySize, SM_NT);
    cudaFuncSetAttribute(attnv_mma,
                         cudaFuncAttributeMaxDynamicSharedMemorySize, SM_NN3);

    const int M = Bk * Sk;           // 8192
    const int* masks[3] = { dmask, smask, gmask };

    // one-time per-launch weight preprocessing
    pack_qkv_kernel<<<(Lk*3*Dk*3*Dk) / 512, 256>>>(attn_w, qkvwhi, qkvwlo);
    pack_qkvb_kernel<<<(Lk*3*3*Dk) / 256, 256>>>(attn_b, qkvb);
    wsplit_kernel<<<(Lk*3*4*Dk*Dk) / 1024, 256>>>(attn_w, awhi, awlo);
    wsplit_kernel<<<(Lk*Dk*FFk) / 1024, 256>>>(ff_w1, f1hi, f1lo);
    wsplit_kernel<<<(Lk*FFk*Dk) / 1024, 256>>>(ff_w2, f2hi, f2lo);
    wsplit_kernel<<<(Dk*Dk) / 1024, 256>>>(out1_w, o1whi, o1wlo);
    wsplit_kernel<<<(Dk*(Dk/2)) / 1024, 256>>>(out2_w, o2whi, o2wlo);

    input_proj_kernel<<<M / 2, 256>>>(x, cond, in_w, in_b, cond_w, cond_b, h);

    for (int l = 0; l < Lk; l++) {
        inorm_kernel<<<M, 256>>>(h, h2hi, h2lo);
        for (int brn = 0; brn < 3; brn++) {
            const int lb = l * 3 + brn;
            const size_t wb = (size_t)lb * 4 * Dk * Dk;
            // fused qkv projection: [8192,512] @ [512,1536]
            wgemm_kernel<false,false,true><<<dim3(12, 64), 256, SM_NN3>>>(
                h2hi, h2lo, qkvwhi + (size_t)lb * Dk * 3 * Dk,
                qkvwlo + (size_t)lb * Dk * 3 * Dk, qkvb + (size_t)lb * 3 * Dk,
                nullptr, qkvhi, qkvlo, M, 3 * Dk, Dk);
            scores_mma<<<dim3(4, 4, Bk*Hh), 256, SM_NT>>>(qkvhi, qkvlo, masks[brn], sc);
            softmax_kernel<<<Bk*Hh*Sk, 256>>>(sc, phi, plo);
            attnv_mma<<<dim3(1, 4, Bk*Hh), 256, SM_NN3>>>(phi, plo, qkvhi, qkvlo, chi, clo);
            wgemm_kernel<false,true,false><<<dim3(4, 64), 256, SM_NN3>>>(
                chi, clo, awhi + wb + 3*Dk*Dk, awlo + wb + 3*Dk*Dk,
                attn_b + (size_t)lb * 4 * Dk + 3 * Dk, h, nullptr, nullptr, M, Dk, Dk);
        }
        inorm_kernel<<<M, 256>>>(h, h2hi, h2lo);
        wgemm_kernel<true,false,true><<<dim3(8, 64), 256, SM_NN3>>>(
            h2hi, h2lo, f1hi + (size_t)l*Dk*FFk, f1lo + (size_t)l*Dk*FFk,
            ff_b1 + (size_t)l*FFk, nullptr, fhi, flo, M, FFk, Dk);
        wgemm_kernel<false,true,false><<<dim3(4, 64), 256, SM_NN3>>>(
            fhi, flo, f2hi + (size_t)l*FFk*Dk, f2lo + (size_t)l*FFk*Dk,
            ff_b2 + (size_t)l*Dk, h, nullptr, nullptr, M, Dk, FFk);
    }

    // output head on tensor cores: split h -> o1 (relu, split) -> o2 (relu fp32)
    split_kernel<<<(M * Dk) / 1024, 256>>>(h, h2hi, h2lo);
    wgemm_kernel<true,false,true><<<dim3(4, 64), 256, SM_NN3>>>(
        h2hi, h2lo, o1whi, o1wlo, out1_b, nullptr, chi, clo, M, Dk, Dk);
    wgemm_kernel<true,false,false><<<dim3(2, 64), 256, SM_NN3>>>(
        chi, clo, o2whi, o2wlo, out2_b, o2, nullptr, nullptr, M, Dk/2, Dk);
    out3_kernel<<<(M * 2 + 255) / 256, 256>>>(o2, out3_w, out3_b, (float*)d_out);
}

// round 5
// speedup vs baseline: 2.8854x; 1.1950x over previous
#include <cuda_runtime.h>
#include <cuda_bf16.h>
#include <cstdint>
#include <math.h>

#define Bk 16
#define Sk 512
#define Dk 512
#define Hh 4
#define DKk 128
#define FFk 1024
#define Lk 4
#define QKVN 4608              // 3 branches x (q|k|v) x 512

typedef __nv_bfloat16 bf16;
typedef __nv_bfloat162 bf162;

// ==================== scratch (device globals; no allocation) ===============
__device__ float g_h  [Bk*Sk*Dk];
__device__ float g_o2 [Bk*Sk*(Dk/2)];
__device__ bf16 g_h2hi[Bk*Sk*Dk],  g_h2lo[Bk*Sk*Dk];
__device__ bf16 g_qkvhi[(size_t)Bk*Sk*QKVN], g_qkvlo[(size_t)Bk*Sk*QKVN];
__device__ bf16 g_ctxhi[(size_t)Bk*Sk*1536], g_ctxlo[(size_t)Bk*Sk*1536];
__device__ bf16 g_fhi [Bk*Sk*FFk], g_flo [Bk*Sk*FFk];
// weights
__device__ bf16 g_qkvwhi[(size_t)Lk*Dk*QKVN], g_qkvwlo[(size_t)Lk*Dk*QKVN];
__device__ float g_qkvb[(size_t)Lk*QKVN];
__device__ bf16 g_wouthi[(size_t)Lk*1536*Dk], g_woutlo[(size_t)Lk*1536*Dk];
__device__ float g_woutb[(size_t)Lk*Dk];
__device__ bf16 g_f1hi[(size_t)Lk*Dk*FFk],    g_f1lo[(size_t)Lk*Dk*FFk];
__device__ bf16 g_f2hi[(size_t)Lk*FFk*Dk],    g_f2lo[(size_t)Lk*FFk*Dk];
__device__ bf16 g_o1whi[Dk*Dk],     g_o1wlo[Dk*Dk];
__device__ bf16 g_o2whi[Dk*(Dk/2)], g_o2wlo[Dk*(Dk/2)];

// ==================== low-level helpers =====================================
__device__ __forceinline__ uint32_t smem_u32(const void* p) {
    return (uint32_t)__cvta_generic_to_shared(p);
}
__device__ __forceinline__ void ldsm4(uint32_t* r, uint32_t addr) {
    asm volatile("ldmatrix.sync.aligned.m8n8.x4.shared.b16 {%0,%1,%2,%3}, [%4];"
        : "=r"(r[0]), "=r"(r[1]), "=r"(r[2]), "=r"(r[3]) : "r"(addr));
}
__device__ __forceinline__ void ldsm4t(uint32_t* r, uint32_t addr) {
    asm volatile("ldmatrix.sync.aligned.m8n8.x4.trans.shared.b16 {%0,%1,%2,%3}, [%4];"
        : "=r"(r[0]), "=r"(r[1]), "=r"(r[2]), "=r"(r[3]) : "r"(addr));
}
__device__ __forceinline__ void mma_bf16(float* c, const uint32_t* a,
                                         uint32_t b0, uint32_t b1) {
    asm volatile("mma.sync.aligned.m16n8k16.row.col.f32.bf16.bf16.f32 "
        "{%0,%1,%2,%3},{%4,%5,%6,%7},{%8,%9},{%0,%1,%2,%3};"
        : "+f"(c[0]), "+f"(c[1]), "+f"(c[2]), "+f"(c[3])
        : "r"(a[0]), "r"(a[1]), "r"(a[2]), "r"(a[3]), "r"(b0), "r"(b1));
}
__device__ __forceinline__ void cp16(uint32_t saddr, const bf16* g) {
    asm volatile("cp.async.cg.shared.global [%0], [%1], 16;"
        :: "r"(saddr), "l"(__cvta_generic_to_global(g)) : "memory");
}
#define CP_COMMIT()   asm volatile("cp.async.commit_group;" ::: "memory")
#define CP_WAIT(n)    asm volatile("cp.async.wait_group %0;" :: "n"(n) : "memory")

__device__ __forceinline__ void split_store2(bf16* hi, bf16* lo, size_t off,
                                             float x, float y) {
    bf16 hx = __float2bfloat16_rn(x);
    bf16 hy = __float2bfloat16_rn(y);
    bf162 hv; hv.x = hx; hv.y = hy;
    *(bf162*)(hi + off) = hv;
    bf162 lv;
    lv.x = __float2bfloat16_rn(x - __bfloat162float(hx));
    lv.y = __float2bfloat16_rn(y - __bfloat162float(hy));
    *(bf162*)(lo + off) = lv;
}
__device__ __forceinline__ void pack_pair(float x, float y,
                                          uint32_t& hi, uint32_t& lo) {
    bf162 h;
    h.x = __float2bfloat16_rn(x);
    h.y = __float2bfloat16_rn(y);
    hi = *(uint32_t*)&h;
    bf162 l;
    l.x = __float2bfloat16_rn(x - __bfloat162float(h.x));
    l.y = __float2bfloat16_rn(y - __bfloat162float(h.y));
    lo = *(uint32_t*)&l;
}

// ==================== smem tile loaders =====================================
// A-style: 128 rows x 32 bf16, pitch 80B
#define TA_BYTES 10240
__device__ __forceinline__ void cpA(uint32_t sbase, const bf16* g, int ld, int tid) {
    #pragma unroll
    for (int i = 0; i < 2; i++) {
        int idx = tid + i * 256;
        int r = idx >> 2, c = idx & 3;
        cp16(sbase + (uint32_t)(r * 80 + c * 16), g + (size_t)r * ld + c * 8);
    }
}
// B NN-style: 32 rows (k) x 128 cols (n), pitch 256B, XOR swizzle
#define TB_BYTES 8192
__device__ __forceinline__ void cpB_nn(uint32_t sbase, const bf16* g, int ld, int tid) {
    #pragma unroll
    for (int i = 0; i < 2; i++) {
        int idx = tid + i * 256;
        int k = idx >> 4, c = idx & 15;
        cp16(sbase + (uint32_t)(k * 256 + ((c ^ (k & 7)) << 4)),
             g + (size_t)k * ld + c * 8);
    }
}

// ==================== bf16x3 compute core (for wgemm) =======================
__device__ __forceinline__ void compute_stage_nn(uint32_t aHi, uint32_t aLo,
        uint32_t bHi, uint32_t bLo, int wm, int wn, int lane, float acc[2][8][4])
{
    #pragma unroll
    for (int s = 0; s < 2; s++) {
        uint32_t ah[2][4], al[2][4], bh[4][4], bl[4][4];
        uint32_t aoff = (uint32_t)((wm + (lane & 15)) * 80 + (s * 2 + (lane >> 4)) * 16);
        ldsm4(ah[0], aHi + aoff);
        ldsm4(ah[1], aHi + aoff + 16 * 80);
        ldsm4(al[0], aLo + aoff);
        ldsm4(al[1], aLo + aoff + 16 * 80);
        int k  = s * 16 + (lane & 7) + ((lane >> 3) & 1) * 8;
        int cb = (wn >> 3) + (lane >> 4);
        uint32_t ro = (uint32_t)(k * 256);
        #pragma unroll
        for (int t = 0; t < 4; t++) {
            uint32_t off = ro + (uint32_t)(((cb + t * 2) ^ (k & 7)) << 4);
            ldsm4t(bh[t], bHi + off);
        }
        #pragma unroll
        for (int mt = 0; mt < 2; mt++)
            #pragma unroll
            for (int j = 0; j < 8; j++) {
                int t = j >> 1, o = j & 1;
                mma_bf16(acc[mt][j], ah[mt], bh[t][o * 2], bh[t][o * 2 + 1]);
                mma_bf16(acc[mt][j], al[mt], bh[t][o * 2], bh[t][o * 2 + 1]);
            }
        #pragma unroll
        for (int t = 0; t < 4; t++) {
            uint32_t off = ro + (uint32_t)(((cb + t * 2) ^ (k & 7)) << 4);
            ldsm4t(bl[t], bLo + off);
        }
        #pragma unroll
        for (int mt = 0; mt < 2; mt++)
            #pragma unroll
            for (int j = 0; j < 8; j++) {
                int t = j >> 1, o = j & 1;
                mma_bf16(acc[mt][j], ah[mt], bl[t][o * 2], bl[t][o * 2 + 1]);
            }
    }
}

// ==================== wgemm: C[M,N] (+)= A[M,K] @ B[K,N], 3-stage ring ======
#define ST_NN   (2 * TA_BYTES + 2 * TB_BYTES)   // 36864
#define SM_NN3  (3 * ST_NN)                     // 110592
template<bool RELU, bool ACCUM, bool OUTSPLIT>
__global__ void __launch_bounds__(256, 2)
wgemm_kernel(const bf16* __restrict__ Ahi, const bf16* __restrict__ Alo,
             const bf16* __restrict__ Bhi, const bf16* __restrict__ Blo,
             const float* __restrict__ bias,
             float* __restrict__ C, bf16* __restrict__ Chi, bf16* __restrict__ Clo,
             int M, int N, int K)
{
    extern __shared__ __align__(128) char smem[];
    const uint32_t sb = smem_u32(smem);
    const int tid = threadIdx.x, lane = tid & 31, w = tid >> 5;
    const int wm = (w & 3) * 32, wn = (w >> 2) * 64;
    const int bm = blockIdx.y * 128, bn = blockIdx.x * 128;
    const int NC = K >> 5;

    float acc[2][8][4];
    #pragma unroll
    for (int i = 0; i < 2; i++)
        #pragma unroll
        for (int j = 0; j < 8; j++)
            #pragma unroll
            for (int q = 0; q < 4; q++) acc[i][j][q] = 0.f;

    const bf16* Agh = Ahi + (size_t)bm * K;
    const bf16* Agl = Alo + (size_t)bm * K;
    const bf16* Bgh = Bhi + bn;
    const bf16* Bgl = Blo + bn;

    auto load = [&](int c, int stg) {
        uint32_t s0 = sb + stg * ST_NN;
        cpA   (s0,                 Agh + c * 32, K, tid);
        cpA   (s0 + TA_BYTES,      Agl + c * 32, K, tid);
        cpB_nn(s0 + 2 * TA_BYTES,            Bgh + (size_t)(c * 32) * N, N, tid);
        cpB_nn(s0 + 2 * TA_BYTES + TB_BYTES, Bgl + (size_t)(c * 32) * N, N, tid);
        CP_COMMIT();
    };

    load(0, 0);
    load(1, 1);
    int stg = 0;
    for (int c = 0; c < NC; c++) {
        if (c + 1 < NC) { CP_WAIT(1); } else { CP_WAIT(0); }
        __syncthreads();
        if (c + 2 < NC) load(c + 2, (stg + 2 > 2) ? stg - 1 : stg + 2);
        uint32_t s0 = sb + stg * ST_NN;
        compute_stage_nn(s0, s0 + TA_BYTES, s0 + 2 * TA_BYTES,
                         s0 + 2 * TA_BYTES + TB_BYTES, wm, wn, lane, acc);
        stg = (stg == 2) ? 0 : stg + 1;
    }

    #pragma unroll
    for (int mt = 0; mt < 2; mt++) {
        int r0 = bm + wm + mt * 16 + (lane >> 2);
        #pragma unroll
        for (int j = 0; j < 8; j++) {
            int col = bn + wn + j * 8 + (lane & 3) * 2;
            float b0 = bias[col], b1 = bias[col + 1];
            float v00 = acc[mt][j][0] + b0, v01 = acc[mt][j][1] + b1;
            float v10 = acc[mt][j][2] + b0, v11 = acc[mt][j][3] + b1;
            size_t o0 = (size_t)r0 * N + col;
            size_t o1 = (size_t)(r0 + 8) * N + col;
            if (ACCUM) {
                float2 c0 = *(const float2*)(C + o0);
                float2 c1 = *(const float2*)(C + o1);
                v00 += c0.x; v01 += c0.y; v10 += c1.x; v11 += c1.y;
            }
            if (RELU) {
                v00 = fmaxf(v00, 0.f); v01 = fmaxf(v01, 0.f);
                v10 = fmaxf(v10, 0.f); v11 = fmaxf(v11, 0.f);
            }
            if (OUTSPLIT) {
                split_store2(Chi, Clo, o0, v00, v01);
                split_store2(Chi, Clo, o1, v10, v11);
            } else {
                float2 r; r.x = v00; r.y = v01; *(float2*)(C + o0) = r;
                float2 s; s.x = v10; s.y = v11; *(float2*)(C + o1) = s;
            }
        }
    }
}

// ==================== flash attention =======================================
// grid (4 qtiles, 64 bh, 3 brn), 256 threads. Warp w owns q-rows w*16..w*16+15.
// smem: Q 4 chunks x (hi,lo) @0 (81920); K 2 stages x (hi,lo) @81920 (40960);
//       V 4 chunks x (hi,lo) @122880 (65536). total 188416.
#define FQB 0
#define FKB 81920
#define FVB 122880
#define FSM 188416

__global__ void __launch_bounds__(256, 1)
flash_kernel(const bf16* __restrict__ qkvhi, const bf16* __restrict__ qkvlo,
             const int* __restrict__ dmask, const int* __restrict__ smask,
             const int* __restrict__ gmask,
             bf16* __restrict__ ctxhi, bf16* __restrict__ ctxlo)
{
    extern __shared__ __align__(128) char smem[];
    const uint32_t sb = smem_u32(smem);
    const int tid = threadIdx.x, lane = tid & 31, w = tid >> 5;
    const int wm = w * 16;
    const int qt = blockIdx.x, bh = blockIdx.y, brn = blockIdx.z;
    const int b = bh >> 2, h = bh & 3;
    const size_t rowbase = (size_t)b * Sk;
    const size_t qoff = (rowbase + qt * 128) * QKVN + brn * 1536 + h * DKk;
    const size_t koff = rowbase * QKVN + brn * 1536 + 512 + h * DKk;
    const size_t voff = rowbase * QKVN + brn * 1536 + 1024 + h * DKk;
    const bf16* Qh = qkvhi + qoff;
    const bf16* Ql = qkvlo + qoff;
    const bf16* Kh = qkvhi + koff;
    const bf16* Kl = qkvlo + koff;
    const bf16* Vh = qkvhi + voff;
    const bf16* Vl = qkvlo + voff;
    const int* mp = ((brn == 0) ? dmask : (brn == 1) ? smask : gmask)
                    + (size_t)b * Sk * Sk;

    // Q resident (group 0)
    #pragma unroll
    for (int c = 0; c < 4; c++) {
        cpA(sb + FQB + c * 20480,         Qh + c * 32, QKVN, tid);
        cpA(sb + FQB + c * 20480 + 10240, Ql + c * 32, QKVN, tid);
    }
    CP_COMMIT();

    auto loadK = [&](int kt, int kc, int stg) {
        const bf16* kh = Kh + (size_t)(kt * 128) * QKVN + kc * 32;
        const bf16* kl = Kl + (size_t)(kt * 128) * QKVN + kc * 32;
        cpA(sb + FKB + stg * 20480,         kh, QKVN, tid);
        cpA(sb + FKB + stg * 20480 + 10240, kl, QKVN, tid);
        CP_COMMIT();
    };
    auto loadV = [&](int kt) {
        #pragma unroll
        for (int vc = 0; vc < 4; vc++) {
            const bf16* vh = Vh + (size_t)(kt * 128 + vc * 32) * QKVN;
            const bf16* vl = Vl + (size_t)(kt * 128 + vc * 32) * QKVN;
            cpB_nn(sb + FVB + vc * 16384,        vh, QKVN, tid);
            cpB_nn(sb + FVB + vc * 16384 + 8192, vl, QKVN, tid);
        }
        CP_COMMIT();
    };

    float m0 = -1e30f, m1 = -1e30f, l0 = 0.f, l1 = 0.f;
    float acc_o[16][4];
    #pragma unroll
    for (int j = 0; j < 16; j++)
        #pragma unroll
        for (int q = 0; q < 4; q++) acc_o[j][q] = 0.f;

    loadK(0, 0, 0);
    loadK(0, 1, 1);

    const float scale = 0.08838834764831845f;  // 1/sqrt(128)
    const int r0loc = qt * 128 + wm + (lane >> 2);

    for (int kt = 0; kt < 4; kt++) {
        float acc_s[16][4];
        #pragma unroll
        for (int j = 0; j < 16; j++)
            #pragma unroll
            for (int q = 0; q < 4; q++) acc_s[j][q] = 0.f;

        // ---- S = Q @ K^T over 4 dk-chunks ----
        for (int kc = 0; kc < 4; kc++) {
            CP_WAIT(1);
            __syncthreads();
            uint32_t QCH = sb + FQB + kc * 20480;
            uint32_t KST = sb + FKB + (kc & 1) * 20480;
            #pragma unroll
            for (int s = 0; s < 2; s++) {
                uint32_t ah[4], al[4];
                uint32_t aoff = QCH + (uint32_t)((wm + (lane & 15)) * 80
                               + (s * 2 + (lane >> 4)) * 16);
                ldsm4(ah, aoff);
                ldsm4(al, aoff + 10240);
                #pragma unroll
                for (int half = 0; half < 2; half++) {
                    uint32_t bh4[4][4], bl4[4][4];
                    #pragma unroll
                    for (int t = 0; t < 4; t++) {
                        int t2 = half * 4 + t;
                        uint32_t boff = KST + (uint32_t)((t2 * 16 + (lane & 15)) * 80
                                       + (s * 2 + (lane >> 4)) * 16);
                        ldsm4(bh4[t], boff);
                    }
                    #pragma unroll
                    for (int t = 0; t < 4; t++)
                        #pragma unroll
                        for (int o = 0; o < 2; o++) {
                            int j = (half * 4 + t) * 2 + o;
                            mma_bf16(acc_s[j], ah, bh4[t][o], bh4[t][o + 2]);
                            mma_bf16(acc_s[j], al, bh4[t][o], bh4[t][o + 2]);
                        }
                    #pragma unroll
                    for (int t = 0; t < 4; t++) {
                        int t2 = half * 4 + t;
                        uint32_t boff = KST + (uint32_t)((t2 * 16 + (lane & 15)) * 80
                                       + (s * 2 + (lane >> 4)) * 16);
                        ldsm4(bl4[t], boff + 10240);
                    }
                    #pragma unroll
                    for (int t = 0; t < 4; t++)
                        #pragma unroll
                        for (int o = 0; o < 2; o++) {
                            int j = (half * 4 + t) * 2 + o;
                            mma_bf16(acc_s[j], ah, bl4[t][o], bl4[t][o + 2]);
                        }
                }
            }
            __syncthreads();
            if (kc < 2)       loadK(kt, kc + 2, kc & 1);
            else if (kc == 2) loadV(kt);
        }

        // ---- mask + scale + online softmax (registers only) ----
        const int* mrow0 = mp + (size_t)r0loc * Sk + kt * 128;
        const int* mrow1 = mrow0 + 8 * Sk;
        float rmax0 = -1e30f, rmax1 = -1e30f;
        #pragma unroll
        for (int j = 0; j < 16; j++) {
            int col = j * 8 + (lane & 3) * 2;
            int2 q0 = *(const int2*)(mrow0 + col);
            int2 q1 = *(const int2*)(mrow1 + col);
            acc_s[j][0] = q0.x ? -1e9f : acc_s[j][0] * scale;
            acc_s[j][1] = q0.y ? -1e9f : acc_s[j][1] * scale;
            acc_s[j][2] = q1.x ? -1e9f : acc_s[j][2] * scale;
            acc_s[j][3] = q1.y ? -1e9f : acc_s[j][3] * scale;
            rmax0 = fmaxf(rmax0, fmaxf(acc_s[j][0], acc_s[j][1]));
            rmax1 = fmaxf(rmax1, fmaxf(acc_s[j][2], acc_s[j][3]));
        }
        rmax0 = fmaxf(rmax0, __shfl_xor_sync(0xffffffffu, rmax0, 1));
        rmax0 = fmaxf(rmax0, __shfl_xor_sync(0xffffffffu, rmax0, 2));
        rmax1 = fmaxf(rmax1, __shfl_xor_sync(0xffffffffu, rmax1, 1));
        rmax1 = fmaxf(rmax1, __shfl_xor_sync(0xffffffffu, rmax1, 2));
        float mn0 = fmaxf(m0, rmax0), mn1 = fmaxf(m1, rmax1);
        float f0 = __expf(m0 - mn0), f1 = __expf(m1 - mn1);
        float rs0 = 0.f, rs1 = 0.f;
        #pragma unroll
        for (int j = 0; j < 16; j++) {
            float p0 = __expf(acc_s[j][0] - mn0);
            float p1 = __expf(acc_s[j][1] - mn0);
            float p2 = __expf(acc_s[j][2] - mn1);
            float p3 = __expf(acc_s[j][3] - mn1);
            acc_s[j][0] = p0; acc_s[j][1] = p1;
            acc_s[j][2] = p2; acc_s[j][3] = p3;
            rs0 += p0 + p1; rs1 += p2 + p3;
        }
        rs0 += __shfl_xor_sync(0xffffffffu, rs0, 1);
        rs0 += __shfl_xor_sync(0xffffffffu, rs0, 2);
        rs1 += __shfl_xor_sync(0xffffffffu, rs1, 1);
        rs1 += __shfl_xor_sync(0xffffffffu, rs1, 2);
        l0 = l0 * f0 + rs0; l1 = l1 * f1 + rs1;
        m0 = mn0; m1 = mn1;
        #pragma unroll
        for (int j = 0; j < 16; j++) {
            acc_o[j][0] *= f0; acc_o[j][1] *= f0;
            acc_o[j][2] *= f1; acc_o[j][3] *= f1;
        }

        // ---- O += P @ V ----
        CP_WAIT(0);
        __syncthreads();
        if (kt < 3) { loadK(kt + 1, 0, 0); loadK(kt + 1, 1, 1); }
        #pragma unroll
        for (int vc = 0; vc < 4; vc++) {
            uint32_t VST = sb + FVB + vc * 16384;
            #pragma unroll
            for (int s = 0; s < 2; s++) {
                int j0 = vc * 4 + s * 2;
                uint32_t ph[4], pl[4];
                pack_pair(acc_s[j0][0],     acc_s[j0][1],     ph[0], pl[0]);
                pack_pair(acc_s[j0][2],     acc_s[j0][3],     ph[1], pl[1]);
                pack_pair(acc_s[j0 + 1][0], acc_s[j0 + 1][1], ph[2], pl[2]);
                pack_pair(acc_s[j0 + 1][2], acc_s[j0 + 1][3], ph[3], pl[3]);
                int lk = s * 16 + (lane & 7) + ((lane >> 3) & 1) * 8;
                int cb = lane >> 4;
                uint32_t ro = VST + (uint32_t)(lk * 256);
                #pragma unroll
                for (int half = 0; half < 2; half++) {
                    uint32_t vh4[4][4], vl4[4][4];
                    #pragma unroll
                    for (int t = 0; t < 4; t++) {
                        int t2 = half * 4 + t;
                        uint32_t off = ro + (uint32_t)(((cb + t2 * 2) ^ (lk & 7)) << 4);
                        ldsm4t(vh4[t], off);
                    }
                    #pragma unroll
                    for (int t = 0; t < 4; t++)
                        #pragma unroll
                        for (int o = 0; o < 2; o++) {
                            int j = (half * 4 + t) * 2 + o;
                            mma_bf16(acc_o[j], ph, vh4[t][o * 2], vh4[t][o * 2 + 1]);
                            mma_bf16(acc_o[j], pl, vh4[t][o * 2], vh4[t][o * 2 + 1]);
                        }
                    #pragma unroll
                    for (int t = 0; t < 4; t++) {
                        int t2 = half * 4 + t;
                        uint32_t off = ro + (uint32_t)(((cb + t2 * 2) ^ (lk & 7)) << 4);
                        ldsm4t(vl4[t], off + 8192);
                    }
                    #pragma unroll
                    for (int t = 0; t < 4; t++)
                        #pragma unroll
                        for (int o = 0; o < 2; o++) {
                            int j = (half * 4 + t) * 2 + o;
                            mma_bf16(acc_o[j], ph, vl4[t][o * 2], vl4[t][o * 2 + 1]);
                        }
                }
            }
        }
        __syncthreads();
    }

    // ---- epilogue: normalize + split-store ctx ----
    float i0 = 1.f / l0, i1 = 1.f / l1;
    size_t gr0 = rowbase + (size_t)r0loc;
    int cc0 = brn * 512 + h * DKk;
    #pragma unroll
    for (int j = 0; j < 16; j++) {
        int col = cc0 + j * 8 + (lane & 3) * 2;
        split_store2(ctxhi, ctxlo, gr0 * 1536 + col,
                     acc_o[j][0] * i0, acc_o[j][1] * i0);
        split_store2(ctxhi, ctxlo, (gr0 + 8) * 1536 + col,
                     acc_o[j][2] * i1, acc_o[j][3] * i1);
    }
}

// ==================== weight pack / split kernels ===========================
__global__ void wsplit_kernel(const float* __restrict__ w, bf16* __restrict__ hi,
                              bf16* __restrict__ lo)
{
    int i = (blockIdx.x * 256 + threadIdx.x) * 4;
    float4 v = *(const float4*)(w + i);
    split_store2(hi, lo, i,     v.x, v.y);
    split_store2(hi, lo, i + 2, v.z, v.w);
}

__global__ void split_kernel(const float* __restrict__ x, bf16* __restrict__ hi,
                             bf16* __restrict__ lo)
{
    int i = (blockIdx.x * 256 + threadIdx.x) * 4;
    float4 v = *(const float4*)(x + i);
    split_store2(hi, lo, i,     v.x, v.y);
    split_store2(hi, lo, i + 2, v.z, v.w);
}

// attn_w [L,3,4,512,512] -> qkvw [L][512][4608], col = brn*1536 + j*512 + n
__global__ void pack_qkv_kernel(const float* __restrict__ aw,
                                bf16* __restrict__ hi, bf16* __restrict__ lo)
{
    size_t o = ((size_t)blockIdx.x * 256 + threadIdx.x) * 2;
    size_t per = (size_t)Dk * QKVN;
    int l = (int)(o / per);
    size_t r = o % per;
    int k = (int)(r / QKVN);
    int c = (int)(r % QKVN);
    int brn = c / 1536, rem = c % 1536;
    int j = rem >> 9, n = rem & 511;
    const float* src = aw + ((((size_t)(l * 3 + brn) * 4 + j) * Dk + k) * Dk + n);
    float2 v = *(const float2*)src;
    split_store2(hi, lo, o, v.x, v.y);
}

__global__ void pack_qkvb_kernel(const float* __restrict__ ab, float* __restrict__ out)
{
    int o = blockIdx.x * 256 + threadIdx.x;   // < Lk*4608
    int l = o / QKVN, c = o % QKVN;
    int brn = c / 1536, rem = c % 1536;
    int j = rem >> 9, n = rem & 511;
    out[o] = ab[((l * 3 + brn) * 4 + j) * Dk + n];
}

// attn_w[...,3,:,:] -> wout [L][1536][512], row = brn*512 + k
__global__ void pack_wout_kernel(const float* __restrict__ aw,
                                 bf16* __restrict__ hi, bf16* __restrict__ lo)
{
    size_t o = ((size_t)blockIdx.x * 256 + threadIdx.x) * 2;
    size_t per = (size_t)1536 * Dk;
    int l = (int)(o / per);
    size_t r = o % per;
    int k = (int)(r / Dk);
    int n = (int)(r % Dk);
    int brn = k / 512, kk = k % 512;
    const float* src = aw + ((((size_t)(l * 3 + brn) * 4 + 3) * Dk + kk) * Dk + n);
    float2 v = *(const float2*)src;
    split_store2(hi, lo, o, v.x, v.y);
}

__global__ void pack_woutb_kernel(const float* __restrict__ ab, float* __restrict__ out)
{
    int o = blockIdx.x * 256 + threadIdx.x;   // < Lk*512
    int l = o / Dk, n = o % Dk;
    float s = 0.f;
    for (int brn = 0; brn < 3; brn++)
        s += ab[((l * 3 + brn) * 4 + 3) * Dk + n];
    out[o] = s;
}

// ==================== reductions ============================================
__device__ __forceinline__ float warpReduceSum(float v) {
    #pragma unroll
    for (int o = 16; o > 0; o >>= 1) v += __shfl_xor_sync(0xffffffffu, v, o);
    return v;
}

// ==================== input projection ======================================
__global__ void input_proj_kernel(const float* __restrict__ x,
                                  const float* __restrict__ cond,
                                  const float* __restrict__ in_w,
                                  const float* __restrict__ in_b,
                                  const float* __restrict__ cond_w,
                                  const float* __restrict__ cond_b,
                                  float* __restrict__ h)
{
    __shared__ float xs[2][18];
    __shared__ float cs[2][89];
    int tok0 = blockIdx.x * 2;
    int t = threadIdx.x;          // 256
    if (t < 36)  xs[t / 18][t % 18] = x[(size_t)tok0 * 18 + t];
    if (t < 178) cs[t / 89][t % 89] = cond[(size_t)tok0 * 89 + t];
    __syncthreads();
    int half = t >> 7, lt = t & 127;
    int col = lt * 4;
    float4 ib = *(const float4*)(in_b + col);
    float4 cbv = *(const float4*)(cond_b + col);
    float a0 = ib.x + cbv.x, a1 = ib.y + cbv.y, a2 = ib.z + cbv.z, a3 = ib.w + cbv.w;
    #pragma unroll 3
    for (int k = 0; k < 18; k++) {
        float4 wv = *(const float4*)(in_w + k * Dk + col);
        float xv = xs[half][k];
        a0 = fmaf(xv, wv.x, a0); a1 = fmaf(xv, wv.y, a1);
        a2 = fmaf(xv, wv.z, a2); a3 = fmaf(xv, wv.w, a3);
    }
    #pragma unroll 3
    for (int k = 0; k < 89; k++) {
        float4 wv = *(const float4*)(cond_w + k * Dk + col);
        float cv = cs[half][k];
        a0 = fmaf(cv, wv.x, a0); a1 = fmaf(cv, wv.y, a1);
        a2 = fmaf(cv, wv.z, a2); a3 = fmaf(cv, wv.w, a3);
    }
    float4 r; r.x = a0; r.y = a1; r.z = a2; r.w = a3;
    *(float4*)(h + (size_t)(tok0 + half) * Dk + col) = r;
}

// ==================== instance norm =========================================
__global__ void inorm_kernel(const float* __restrict__ x,
                             bf16* __restrict__ yhi, bf16* __restrict__ ylo)
{
    __shared__ float s1[8], s2[8];
    const size_t base = (size_t)blockIdx.x * Dk;
    int t = threadIdx.x;          // 256
    float a = x[base + t], b = x[base + t + 256];
    float sum = warpReduceSum(a + b);
    float sq  = warpReduceSum(a * a + b * b);
    if ((t & 31) == 0) { s1[t >> 5] = sum; s2[t >> 5] = sq; }
    __syncthreads();
    if (t < 32) {
        float v1 = (t < 8) ? s1[t] : 0.f;
        float v2 = (t < 8) ? s2[t] : 0.f;
        v1 = warpReduceSum(v1);
        v2 = warpReduceSum(v2);
        if (t == 0) { s1[0] = v1; s2[0] = v2; }
    }
    __syncthreads();
    float mean = s1[0] * (1.f / Dk);
    float var  = s2[0] * (1.f / Dk) - mean * mean;
    float r = rsqrtf(var + 1e-5f);
    float y0 = (a - mean) * r, y1 = (b - mean) * r;
    bf16 h0 = __float2bfloat16_rn(y0);
    bf16 h1 = __float2bfloat16_rn(y1);
    yhi[base + t]       = h0;
    yhi[base + t + 256] = h1;
    ylo[base + t]       = __float2bfloat16_rn(y0 - __bfloat162float(h0));
    ylo[base + t + 256] = __float2bfloat16_rn(y1 - __bfloat162float(h1));
}

// ==================== final tiny head =======================================
__global__ void out3_kernel(const float* __restrict__ o2,
                            const float* __restrict__ w,
                            const float* __restrict__ b,
                            float* __restrict__ out)
{
    int idx = blockIdx.x * 256 + threadIdx.x;
    if (idx >= Bk * Sk * 2) return;
    int tok = idx >> 1, j = idx & 1;
    const float* o = o2 + (size_t)tok * 256;
    float acc = b[j];
    #pragma unroll 8
    for (int kk = 0; kk < 256; kk++) acc = fmaf(o[kk], w[kk * 2 + j], acc);
    out[idx] = acc;
}

// ============================ host launcher =================================
extern "C" void kernel_launch(void* const* d_in, const int* in_sizes, int n_in,
                              void* d_out, int out_size)
{
    const float* x      = (const float*)d_in[0];
    const float* cond   = (const float*)d_in[1];
    const int*   dmask  = (const int*)  d_in[2];
    const int*   smask  = (const int*)  d_in[3];
    const int*   gmask  = (const int*)  d_in[4];
    const float* attn_w = (const float*)d_in[5];
    const float* attn_b = (const float*)d_in[6];
    const float* ff_w1  = (const float*)d_in[7];
    const float* ff_b1  = (const float*)d_in[8];
    const float* ff_w2  = (const float*)d_in[9];
    const float* ff_b2  = (const float*)d_in[10];
    const float* in_w   = (const float*)d_in[11];
    const float* in_b   = (const float*)d_in[12];
    const float* cond_w = (const float*)d_in[13];
    const float* cond_b = (const float*)d_in[14];
    const float* out1_w = (const float*)d_in[15];
    const float* out1_b = (const float*)d_in[16];
    const float* out2_w = (const float*)d_in[17];
    const float* out2_b = (const float*)d_in[18];
    const float* out3_w = (const float*)d_in[19];
    const float* out3_b = (const float*)d_in[20];

    float *h, *o2, *qkvb, *woutb;
    bf16 *h2hi, *h2lo, *qkvhi, *qkvlo, *ctxhi, *ctxlo, *fhi, *flo;
    bf16 *qkvwhi, *qkvwlo, *wouthi, *woutlo, *f1hi, *f1lo, *f2hi, *f2lo;
    bf16 *o1whi, *o1wlo, *o2whi, *o2wlo;
    cudaGetSymbolAddress((void**)&h,      g_h);
    cudaGetSymbolAddress((void**)&o2,     g_o2);
    cudaGetSymbolAddress((void**)&qkvb,   g_qkvb);
    cudaGetSymbolAddress((void**)&woutb,  g_woutb);
    cudaGetSymbolAddress((void**)&h2hi,   g_h2hi);
    cudaGetSymbolAddress((void**)&h2lo,   g_h2lo);
    cudaGetSymbolAddress((void**)&qkvhi,  g_qkvhi);
    cudaGetSymbolAddress((void**)&qkvlo,  g_qkvlo);
    cudaGetSymbolAddress((void**)&ctxhi,  g_ctxhi);
    cudaGetSymbolAddress((void**)&ctxlo,  g_ctxlo);
    cudaGetSymbolAddress((void**)&fhi,    g_fhi);
    cudaGetSymbolAddress((void**)&flo,    g_flo);
    cudaGetSymbolAddress((void**)&qkvwhi, g_qkvwhi);
    cudaGetSymbolAddress((void**)&qkvwlo, g_qkvwlo);
    cudaGetSymbolAddress((void**)&wouthi, g_wouthi);
    cudaGetSymbolAddress((void**)&woutlo, g_woutlo);
    cudaGetSymbolAddress((void**)&f1hi,   g_f1hi);
    cudaGetSymbolAddress((void**)&f1lo,   g_f1lo);
    cudaGetSymbolAddress((void**)&f2hi,   g_f2hi);
    cudaGetSymbolAddress((void**)&f2lo,   g_f2lo);
    cudaGetSymbolAddress((void**)&o1whi,  g_o1whi);
    cudaGetSymbolAddress((void**)&o1wlo,  g_o1wlo);
    cudaGetSymbolAddress((void**)&o2whi,  g_o2whi);
    cudaGetSymbolAddress((void**)&o2wlo,  g_o2wlo);

    cudaFuncSetAttribute(wgemm_kernel<false,false,true>,
                         cudaFuncAttributeMaxDynamicSharedMemorySize, SM_NN3);
    cudaFuncSetAttribute(wgemm_kernel<true,false,true>,
                         cudaFuncAttributeMaxDynamicSharedMemorySize, SM_NN3);
    cudaFuncSetAttribute(wgemm_kernel<false,true,false>,
                         cudaFuncAttributeMaxDynamicSharedMemorySize, SM_NN3);
    cudaFuncSetAttribute(wgemm_kernel<true,false,false>,
                         cudaFuncAttributeMaxDynamicSharedMemorySize, SM_NN3);
    cudaFuncSetAttribute(flash_kernel,
                         cudaFuncAttributeMaxDynamicSharedMemorySize, FSM);

    const int M = Bk * Sk;           // 8192

    // one-time per-launch weight preprocessing
    pack_qkv_kernel<<<(int)(((size_t)Lk*Dk*QKVN) / 512), 256>>>(attn_w, qkvwhi, qkvwlo);
    pack_qkvb_kernel<<<(Lk*QKVN) / 256, 256>>>(attn_b, qkvb);
    pack_wout_kernel<<<(int)(((size_t)Lk*1536*Dk) / 512), 256>>>(attn_w, wouthi, woutlo);
    pack_woutb_kernel<<<(Lk*Dk) / 256, 256>>>(attn_b, woutb);
    wsplit_kernel<<<(Lk*Dk*FFk) / 1024, 256>>>(ff_w1, f1hi, f1lo);
    wsplit_kernel<<<(Lk*FFk*Dk) / 1024, 256>>>(ff_w2, f2hi, f2lo);
    wsplit_kernel<<<(Dk*Dk) / 1024, 256>>>(out1_w, o1whi, o1wlo);
    wsplit_kernel<<<(Dk*(Dk/2)) / 1024, 256>>>(out2_w, o2whi, o2wlo);

    input_proj_kernel<<<M / 2, 256>>>(x, cond, in_w, in_b, cond_w, cond_b, h);

    for (int l = 0; l < Lk; l++) {
        inorm_kernel<<<M, 256>>>(h, h2hi, h2lo);
        // fused qkv for all 3 branches: [8192,512] @ [512,4608]
        wgemm_kernel<false,false,true><<<dim3(QKVN/128, 64), 256, SM_NN3>>>(
            h2hi, h2lo, qkvwhi + (size_t)l * Dk * QKVN,
            qkvwlo + (size_t)l * Dk * QKVN, qkvb + (size_t)l * QKVN,
            nullptr, qkvhi, qkvlo, M, QKVN, Dk);
        // flash attention: all branches, heads, q-tiles
        flash_kernel<<<dim3(4, Bk*Hh, 3), 256, FSM>>>(
            qkvhi, qkvlo, dmask, smask, gmask, ctxhi, ctxlo);
        // batched out-projection: h += ctx[8192,1536] @ wout[1536,512]
        wgemm_kernel<false,true,false><<<dim3(4, 64), 256, SM_NN3>>>(
            ctxhi, ctxlo, wouthi + (size_t)l * 1536 * Dk,
            woutlo + (size_t)l * 1536 * Dk, woutb + (size_t)l * Dk,
            h, nullptr, nullptr, M, Dk, 1536);
        inorm_kernel<<<M, 256>>>(h, h2hi, h2lo);
        wgemm_kernel<true,false,true><<<dim3(8, 64), 256, SM_NN3>>>(
            h2hi, h2lo, f1hi + (size_t)l*Dk*FFk, f1lo + (size_t)l*Dk*FFk,
            ff_b1 + (size_t)l*FFk, nullptr, fhi, flo, M, FFk, Dk);
        wgemm_kernel<false,true,false><<<dim3(4, 64), 256, SM_NN3>>>(
            fhi, flo, f2hi + (size_t)l*FFk*Dk, f2lo + (size_t)l*FFk*Dk,
            ff_b2 + (size_t)l*Dk, h, nullptr, nullptr, M, Dk, FFk);
    }

    // output head on tensor cores
    split_kernel<<<(M * Dk) / 1024, 256>>>(h, h2hi, h2lo);
    wgemm_kernel<true,false,true><<<dim3(4, 64), 256, SM_NN3>>>(
        h2hi, h2lo, o1whi, o1wlo, out1_b, nullptr, ctxhi, ctxlo, M, Dk, Dk);
    wgemm_kernel<true,false,false><<<dim3(2, 64), 256, SM_NN3>>>(
        ctxhi, ctxlo, o2whi, o2wlo, out2_b, o2, nullptr, nullptr, M, Dk/2, Dk);
    out3_kernel<<<(M * 2 + 255) / 256, 256>>>(o2, out3_w, out3_b, (float*)d_out);
}